// round 12
// baseline (speedup 1.0000x reference)
#include <cuda_runtime.h>
#include <cuda_bf16.h>
#include <cuda_fp16.h>
#include <cstdint>
#include <math.h>

// ---------------------------------------------------------------------------
// Problem constants
// ---------------------------------------------------------------------------
#define NROWS 65536
#define DK    512
#define HH    256
#define H2    128
#define O3    64
#define NRB1  512           // gemm1 row blocks of 128
#define NRB2  1024          // fused2 row blocks of 64

// ---------------------------------------------------------------------------
// Scratch (device globals — allocation-free per harness rules)
// ---------------------------------------------------------------------------
__device__ __align__(16) __half g_hraw[2 * NROWS * HH];   // 64 MB fp16 pre-BN
__device__ float g_psum[2 * NRB1 * HH];
__device__ float g_psq [2 * NRB1 * HH];
__device__ float g_scale[2 * HH];
__device__ float g_shift[2 * HH];
// All weights single fp16, transposed K-major [N][K]
__device__ __align__(16) __half g_w1[HH * DK];
__device__ __align__(16) __half g_w2[H2 * HH];
__device__ __align__(16) __half g_w3[O3 * 384];

// ---------------------------------------------------------------------------
// Warp-MMA helpers (base PTX — no sm_103a-only features)
// ---------------------------------------------------------------------------
__device__ __forceinline__ uint32_t smem_u32(const void* p) {
    uint32_t a;
    asm("{ .reg .u64 t; cvta.to.shared.u64 t, %1; cvt.u32.u64 %0, t; }"
        : "=r"(a) : "l"(p));
    return a;
}

__device__ __forceinline__ void mma_f16(float& c0, float& c1, float& c2, float& c3,
                                        uint32_t a0, uint32_t a1, uint32_t a2, uint32_t a3,
                                        uint32_t b0, uint32_t b1) {
    asm volatile(
        "mma.sync.aligned.m16n8k16.row.col.f32.f16.f16.f32 "
        "{%0,%1,%2,%3}, {%4,%5,%6,%7}, {%8,%9}, {%0,%1,%2,%3};"
        : "+f"(c0), "+f"(c1), "+f"(c2), "+f"(c3)
        : "r"(a0), "r"(a1), "r"(a2), "r"(a3), "r"(b0), "r"(b1));
}

__device__ __forceinline__ void ldmatrix_x4(uint32_t* r, uint32_t addr) {
    asm volatile("ldmatrix.sync.aligned.m8n8.x4.shared.b16 {%0,%1,%2,%3}, [%4];"
        : "=r"(r[0]), "=r"(r[1]), "=r"(r[2]), "=r"(r[3]) : "r"(addr));
}

__device__ __forceinline__ void ldmatrix_x2(uint32_t* r, uint32_t addr) {
    asm volatile("ldmatrix.sync.aligned.m8n8.x2.shared.b16 {%0,%1}, [%2];"
        : "=r"(r[0]), "=r"(r[1]) : "r"(addr));
}

__device__ __forceinline__ void cpasync16(uint32_t dst, const void* src) {
    asm volatile("cp.async.cg.shared.global [%0], [%1], 16;" :: "r"(dst), "l"(src));
}
__device__ __forceinline__ void cpasync_commit() {
    asm volatile("cp.async.commit_group;" ::: "memory");
}
__device__ __forceinline__ void cpasync_wait0() {
    asm volatile("cp.async.wait_group 0;" ::: "memory");
}

// pack (x,y) into one fp16x2 word
__device__ __forceinline__ uint32_t pack_h2(float x, float y) {
    __half2 h = __floats2half2_rn(x, y);
    return *reinterpret_cast<uint32_t*>(&h);
}

__device__ __forceinline__ float2 unpack_h2(uint32_t u) {
    __half2 h = *reinterpret_cast<__half2*>(&u);
    return __half22float2(h);
}

// ---------------------------------------------------------------------------
// Weight prep: transpose to K-major fp16. W1[256][512], W2[128][256], W3[64][384].
// ---------------------------------------------------------------------------
__global__ void prep_weights(const float* __restrict__ W1,
                             const float* __restrict__ W2,
                             const float* __restrict__ W3)
{
    int i = blockIdx.x * 256 + threadIdx.x;
    if (i < DK * HH) {
        int k = i >> 8, n = i & 255;
        g_w1[n * DK + k] = __float2half_rn(W1[i]);
        return;
    }
    int j = i - DK * HH;
    if (j < HH * H2) {
        int k = j >> 7, n = j & 127;
        g_w2[n * HH + k] = __float2half_rn(W2[j]);
        return;
    }
    int j2 = j - HH * H2;
    if (j2 < 384 * O3) {
        int k = j2 >> 6, n = j2 & 63;
        g_w3[n * 384 + k] = __float2half_rn(W3[j2]);
    }
}

// ---------------------------------------------------------------------------
// GEMM1 v7 (mma.sync fp16, single pass): hraw(fp16) = X @ W1 + b1, plus stats.
// CTA 128x256 (halves W1 L2 refetch), 256 threads, 8 warps (2m x 4n),
// warp tile 64x64 (32:12 MMA:LDSM). K-chunks of 64, double-buffered.
// ---------------------------------------------------------------------------
#define AST 72
#define G1_AB  (128 * AST * 2)                // 18432
#define G1_BB  (256 * AST * 2)                // 36864
#define G1_STAGE (G1_AB + G1_BB)              // 55296
#define G1_DYN   (2 * G1_STAGE)               // 110592

__global__ void __launch_bounds__(256) gemm1_mma(
    const float* __restrict__ x1, const float* __restrict__ x2,
    const float* __restrict__ b1)
{
    extern __shared__ char dyn[];
    const int z    = blockIdx.y;
    const int rb   = blockIdx.x;
    const int row0 = rb * 128;
    const float* __restrict__ X = z ? x2 : x1;

    const int tid  = threadIdx.x;
    const int lane = tid & 31;
    const int wid  = tid >> 5;
    const int wm   = wid >> 2;       // 0..1
    const int wn   = wid & 3;        // 0..3
    const int g    = lane >> 2;      // 0..7
    const int tg   = lane & 3;       // 0..3
    const int ln16 = lane & 15;
    const int lhalf = (lane >> 4) & 1;

    float acc[4][8][4];
#pragma unroll
    for (int t = 0; t < 4; t++)
#pragma unroll
        for (int u = 0; u < 8; u++)
#pragma unroll
            for (int j = 0; j < 4; j++) acc[t][u][j] = 0.0f;

    float4 aNext[8];

#define G1_LDA(c) do { \
        const int kk_ = (c) * 64; \
        _Pragma("unroll") \
        for (int it = 0; it < 8; it++) { \
            int idx = tid + it * 256; \
            int r_  = idx >> 4, c4_ = idx & 15; \
            aNext[it] = *reinterpret_cast<const float4*>( \
                X + (size_t)(row0 + r_) * DK + kk_ + c4_ * 4); \
        } \
    } while (0)

#define G1_STA(stg) do { \
        char* sAh_ = dyn + (stg) * G1_STAGE; \
        _Pragma("unroll") \
        for (int it = 0; it < 8; it++) { \
            int idx = tid + it * 256; \
            int r_  = idx >> 4, c4_ = idx & 15; \
            uint32_t p0 = pack_h2(aNext[it].x, aNext[it].y); \
            uint32_t p1 = pack_h2(aNext[it].z, aNext[it].w); \
            int off = (r_ * AST + c4_ * 4) * 2; \
            *reinterpret_cast<uint2*>(sAh_ + off) = make_uint2(p0, p1); \
        } \
    } while (0)

#define G1_CPB(c, stg) do { \
        const int kk_ = (c) * 64; \
        char* sB_ = dyn + (stg) * G1_STAGE + G1_AB; \
        uint32_t bU = smem_u32(sB_); \
        _Pragma("unroll") \
        for (int it = 0; it < 8; it++) { \
            int idx = tid + it * 256; \
            int n_ = idx >> 3, c8_ = idx & 7; \
            int off = (n_ * AST + c8_ * 8) * 2; \
            cpasync16(bU + off, g_w1 + (size_t)n_ * DK + kk_ + c8_ * 8); \
        } \
        cpasync_commit(); \
    } while (0)

    G1_CPB(0, 0);
    G1_LDA(0);
    G1_STA(0);
    cpasync_wait0();
    __syncthreads();

    const int NC = DK / 64;   // 8
    for (int c = 0; c < NC; c++) {
        const int s = c & 1;
        if (c + 1 < NC) {
            G1_CPB(c + 1, s ^ 1);
            G1_LDA(c + 1);
        }

        {
            char* st = dyn + s * G1_STAGE;
            uint32_t sAhU = smem_u32(st);
            uint32_t sBU  = sAhU + G1_AB;

            const uint32_t aOff = ((wm * 64 + ln16) * AST + lhalf * 8) * 2;
            const uint32_t bOff = (((wn * 64 + (ln16 & 7)) * AST) + ((ln16 >> 3) * 8)) * 2;

#pragma unroll
            for (int ks = 0; ks < 4; ks++) {
                const uint32_t ko = ks * 32;
                uint32_t Ah[4][4], Bh[8][2];
#pragma unroll
                for (int t = 0; t < 4; t++)
                    ldmatrix_x4(Ah[t], sAhU + aOff + (t * 16 * AST) * 2 + ko);
#pragma unroll
                for (int u = 0; u < 8; u++)
                    ldmatrix_x2(Bh[u], sBU + bOff + (u * 8 * AST) * 2 + ko);
#pragma unroll
                for (int t = 0; t < 4; t++)
#pragma unroll
                    for (int u = 0; u < 8; u++)
                        mma_f16(acc[t][u][0], acc[t][u][1], acc[t][u][2], acc[t][u][3],
                                Ah[t][0], Ah[t][1], Ah[t][2], Ah[t][3],
                                Bh[u][0], Bh[u][1]);
            }
        }

        if (c + 1 < NC) {
            G1_STA(s ^ 1);
            cpasync_wait0();
            __syncthreads();
        }
    }

    // ---- epilogue: bias, store hraw (fp16), column partial stats ----
    float css0[8], css1[8], cqq0[8], cqq1[8];
#pragma unroll
    for (int u = 0; u < 8; u++) {
        const int col = wn * 64 + u * 8 + tg * 2;
        const float bi0 = b1[col], bi1 = b1[col + 1];
        float cs0 = 0.f, cs1 = 0.f, cq0 = 0.f, cq1 = 0.f;
#pragma unroll
        for (int t = 0; t < 4; t++) {
            const int r = row0 + wm * 64 + t * 16 + g;
            float v0 = acc[t][u][0] + bi0;
            float v1 = acc[t][u][1] + bi1;
            float v2 = acc[t][u][2] + bi0;
            float v3 = acc[t][u][3] + bi1;
            *reinterpret_cast<uint32_t*>(
                &g_hraw[((size_t)z * NROWS + r) * HH + col])     = pack_h2(v0, v1);
            *reinterpret_cast<uint32_t*>(
                &g_hraw[((size_t)z * NROWS + r + 8) * HH + col]) = pack_h2(v2, v3);
            cs0 += v0 + v2; cs1 += v1 + v3;
            cq0 += v0 * v0 + v2 * v2; cq1 += v1 * v1 + v3 * v3;
        }
        css0[u] = cs0; css1[u] = cs1; cqq0[u] = cq0; cqq1[u] = cq1;
    }
#pragma unroll
    for (int off = 4; off < 32; off <<= 1) {
#pragma unroll
        for (int u = 0; u < 8; u++) {
            css0[u] += __shfl_xor_sync(0xffffffffu, css0[u], off);
            css1[u] += __shfl_xor_sync(0xffffffffu, css1[u], off);
            cqq0[u] += __shfl_xor_sync(0xffffffffu, cqq0[u], off);
            cqq1[u] += __shfl_xor_sync(0xffffffffu, cqq1[u], off);
        }
    }
    // combine the two wm halves via smem (stage memory is free now)
    float* s_ps = reinterpret_cast<float*>(dyn);          // [2][256]
    float* s_sq = s_ps + 512;
    __syncthreads();
    if (g == 0) {
#pragma unroll
        for (int u = 0; u < 8; u++) {
            const int col = wn * 64 + u * 8 + tg * 2;
            s_ps[wm * 256 + col]     = css0[u];
            s_ps[wm * 256 + col + 1] = css1[u];
            s_sq[wm * 256 + col]     = cqq0[u];
            s_sq[wm * 256 + col + 1] = cqq1[u];
        }
    }
    __syncthreads();
    {
        const size_t base = ((size_t)z * NRB1 + rb) * HH + tid;
        g_psum[base] = s_ps[tid] + s_ps[256 + tid];
        g_psq [base] = s_sq[tid] + s_sq[256 + tid];
    }
#undef G1_LDA
#undef G1_STA
#undef G1_CPB
}

// ---------------------------------------------------------------------------
// Stats: one block per (z, column); 256 threads reduce NRB1 partials.
// ---------------------------------------------------------------------------
__global__ void __launch_bounds__(256) stats_kernel(
    const float* __restrict__ gamma, const float* __restrict__ beta_bn)
{
    const int z = blockIdx.x >> 8;
    const int c = blockIdx.x & 255;
    const int tid = threadIdx.x;

    float s = 0.0f, q = 0.0f;
    for (int i = tid; i < NRB1; i += 256) {
        s += g_psum[((size_t)z * NRB1 + i) * HH + c];
        q += g_psq [((size_t)z * NRB1 + i) * HH + c];
    }
#pragma unroll
    for (int off = 16; off > 0; off >>= 1) {
        s += __shfl_xor_sync(0xffffffffu, s, off);
        q += __shfl_xor_sync(0xffffffffu, q, off);
    }
    __shared__ float rs[8], rq[8];
    if ((tid & 31) == 0) { rs[tid >> 5] = s; rq[tid >> 5] = q; }
    __syncthreads();
    if (tid == 0) {
        float S = 0.f, Q = 0.f;
#pragma unroll
        for (int w = 0; w < 8; w++) { S += rs[w]; Q += rq[w]; }
        const float mean = S / (float)NROWS;
        const float var  = Q / (float)NROWS - mean * mean;
        const float sc   = gamma[c] * rsqrtf(var + 1e-5f);
        g_scale[z * HH + c] = sc;
        g_shift[z * HH + c] = beta_bn[c] - mean * sc;
    }
}

// ---------------------------------------------------------------------------
// FUSED v4 (unchanged from Round 11, passing): 64-row CTAs, 2 CTAs/SM.
// 8 warps (2m x 4n): GEMM2 warp tile 32x32, GEMM3 warp tile 32x16.
// ---------------------------------------------------------------------------
#define F2_AB   (64 * AST * 2)         // 9216 (single A stage)
#define F2_AREG (2 * F2_AB)            // 18432
#define F2_BB   (128 * AST * 2)        // 18432
#define F2_BREG (2 * F2_BB)            // 36864
#define F2_DYN  (F2_AREG + F2_BREG)    // 55296
#define ST3 136

__global__ void __launch_bounds__(256, 2) fused2(
    const float* __restrict__ b2, const float* __restrict__ b3,
    const float* __restrict__ W4, const float* __restrict__ b4,
    const float* __restrict__ alphap, const float* __restrict__ betap,
    float* __restrict__ out)
{
    extern __shared__ char dyn[];
    __shared__ float s_sc[HH];
    __shared__ float s_sh[HH];
    __shared__ float s_red[4][64][4];

    const int rb   = blockIdx.x;
    const int row0 = rb * 64;
    const int tid  = threadIdx.x;
    const int lane = tid & 31;
    const int wid  = tid >> 5;
    const int wm   = wid >> 2;       // 0..1
    const int wn   = wid & 3;        // 0..3
    const int g    = lane >> 2;
    const int tg   = lane & 3;
    const int ln16 = lane & 15;
    const int lhalf = (lane >> 4) & 1;

    char* Areg = dyn;
    char* Breg = dyn + F2_AREG;

    float acc[2][4][4];
    float h1[2][4][4];
    uint4 aNext[2];

    const uint32_t aOff2 = ((wm * 32 + ln16) * AST + lhalf * 8) * 2;
    const uint32_t bOff2 = (((wn * 32 + (ln16 & 7)) * AST) + ((ln16 >> 3) * 8)) * 2;

#define F2_LDA(zz, c) do { \
        const int kk_ = (c) * 64; \
        _Pragma("unroll") \
        for (int it = 0; it < 2; it++) { \
            int idx = tid + it * 256; \
            int r_  = idx >> 3, c8_ = idx & 7; \
            aNext[it] = *reinterpret_cast<const uint4*>( \
                g_hraw + ((size_t)(zz) * NROWS + row0 + r_) * HH + kk_ + c8_ * 8); \
        } \
    } while (0)

#define F2_STA(c, stg) do { \
        const int kk_ = (c) * 64; \
        char* sA_ = Areg + (stg) * F2_AB; \
        _Pragma("unroll") \
        for (int it = 0; it < 2; it++) { \
            int idx = tid + it * 256; \
            int r_  = idx >> 3, c8_ = idx & 7; \
            const int col_ = kk_ + c8_ * 8; \
            float2 f0 = unpack_h2(aNext[it].x); \
            float2 f1 = unpack_h2(aNext[it].y); \
            float2 f2 = unpack_h2(aNext[it].z); \
            float2 f3 = unpack_h2(aNext[it].w); \
            float a0 = fmaxf(s_sc[col_ + 0] * f0.x + s_sh[col_ + 0], 0.0f); \
            float a1 = fmaxf(s_sc[col_ + 1] * f0.y + s_sh[col_ + 1], 0.0f); \
            float a2 = fmaxf(s_sc[col_ + 2] * f1.x + s_sh[col_ + 2], 0.0f); \
            float a3 = fmaxf(s_sc[col_ + 3] * f1.y + s_sh[col_ + 3], 0.0f); \
            float a4 = fmaxf(s_sc[col_ + 4] * f2.x + s_sh[col_ + 4], 0.0f); \
            float a5 = fmaxf(s_sc[col_ + 5] * f2.y + s_sh[col_ + 5], 0.0f); \
            float a6 = fmaxf(s_sc[col_ + 6] * f3.x + s_sh[col_ + 6], 0.0f); \
            float a7 = fmaxf(s_sc[col_ + 7] * f3.y + s_sh[col_ + 7], 0.0f); \
            int off = (r_ * AST + c8_ * 8) * 2; \
            *reinterpret_cast<uint4*>(sA_ + off) = \
                make_uint4(pack_h2(a0, a1), pack_h2(a2, a3), \
                           pack_h2(a4, a5), pack_h2(a6, a7)); \
        } \
    } while (0)

#define F2_CPB(c, stg) do { \
        const int kk_ = (c) * 64; \
        char* sB_ = Breg + (stg) * F2_BB; \
        uint32_t bU = smem_u32(sB_); \
        _Pragma("unroll") \
        for (int it = 0; it < 4; it++) { \
            int idx = tid + it * 256; \
            int n_ = idx >> 3, c8_ = idx & 7; \
            int off = (n_ * AST + c8_ * 8) * 2; \
            cpasync16(bU + off, g_w2 + (size_t)n_ * HH + kk_ + c8_ * 8); \
        } \
        cpasync_commit(); \
    } while (0)

    // ========================= Phases 1 & 2: GEMM2 x2 =======================
    for (int z = 0; z < 2; z++) {
        __syncthreads();
        s_sc[tid] = g_scale[z * HH + tid];
        s_sh[tid] = g_shift[z * HH + tid];
        __syncthreads();

#pragma unroll
        for (int t = 0; t < 2; t++)
#pragma unroll
            for (int u = 0; u < 4; u++)
#pragma unroll
                for (int j = 0; j < 4; j++) acc[t][u][j] = 0.0f;

        F2_CPB(0, 0);
        F2_LDA(z, 0);
        F2_STA(0, 0);
        cpasync_wait0();
        __syncthreads();

        const int NC = 4;
        for (int c = 0; c < NC; c++) {
            const int s = c & 1;
            if (c + 1 < NC) {
                F2_CPB(c + 1, s ^ 1);
                F2_LDA(z, c + 1);
            }
            {
                uint32_t sAU = smem_u32(Areg + s * F2_AB);
                uint32_t sBU = smem_u32(Breg + s * F2_BB);
#pragma unroll
                for (int ks = 0; ks < 4; ks++) {
                    const uint32_t ko = ks * 32;
                    uint32_t Ah[2][4], Bh[4][2];
#pragma unroll
                    for (int t = 0; t < 2; t++)
                        ldmatrix_x4(Ah[t], sAU + aOff2 + (t * 16 * AST) * 2 + ko);
#pragma unroll
                    for (int u = 0; u < 4; u++)
                        ldmatrix_x2(Bh[u], sBU + bOff2 + (u * 8 * AST) * 2 + ko);
#pragma unroll
                    for (int t = 0; t < 2; t++)
#pragma unroll
                        for (int u = 0; u < 4; u++)
                            mma_f16(acc[t][u][0], acc[t][u][1], acc[t][u][2], acc[t][u][3],
                                    Ah[t][0], Ah[t][1], Ah[t][2], Ah[t][3],
                                    Bh[u][0], Bh[u][1]);
                }
            }
            if (c + 1 < NC) {
                __syncthreads();
                F2_STA(c + 1, s ^ 1);
                cpasync_wait0();
                __syncthreads();
            }
        }

        // epilogue: h = relu(acc + b2); stash into h1 (z=0) or keep in acc (z=1)
#pragma unroll
        for (int u = 0; u < 4; u++) {
            const int col = wn * 32 + u * 8 + tg * 2;
            const float bi0 = b2[col], bi1 = b2[col + 1];
#pragma unroll
            for (int t = 0; t < 2; t++) {
                float v0 = fmaxf(acc[t][u][0] + bi0, 0.0f);
                float v1 = fmaxf(acc[t][u][1] + bi1, 0.0f);
                float v2 = fmaxf(acc[t][u][2] + bi0, 0.0f);
                float v3 = fmaxf(acc[t][u][3] + bi1, 0.0f);
                if (z == 0) {
                    h1[t][u][0] = v0; h1[t][u][1] = v1;
                    h1[t][u][2] = v2; h1[t][u][3] = v3;
                } else {
                    acc[t][u][0] = v0; acc[t][u][1] = v1;
                    acc[t][u][2] = v2; acc[t][u][3] = v3;
                }
            }
        }
    }

    // ================== cosine partials (row-wise) from fragments ==========
    {
        float dotR[4], n1R[4], n2R[4];
#pragma unroll
        for (int ri = 0; ri < 4; ri++) { dotR[ri] = 0.f; n1R[ri] = 0.f; n2R[ri] = 0.f; }
#pragma unroll
        for (int t = 0; t < 2; t++)
#pragma unroll
            for (int u = 0; u < 4; u++)
#pragma unroll
                for (int j = 0; j < 4; j++) {
                    const float a = h1[t][u][j];
                    const float b = acc[t][u][j];
                    const int ri = t * 2 + (j >> 1);
                    dotR[ri] = fmaf(a, b, dotR[ri]);
                    n1R[ri]  = fmaf(a, a, n1R[ri]);
                    n2R[ri]  = fmaf(b, b, n2R[ri]);
                }
#pragma unroll
        for (int off = 1; off < 4; off <<= 1) {
#pragma unroll
            for (int ri = 0; ri < 4; ri++) {
                dotR[ri] += __shfl_xor_sync(0xffffffffu, dotR[ri], off);
                n1R[ri]  += __shfl_xor_sync(0xffffffffu, n1R[ri], off);
                n2R[ri]  += __shfl_xor_sync(0xffffffffu, n2R[ri], off);
            }
        }
        if (tg == 0) {
#pragma unroll
            for (int ri = 0; ri < 4; ri++) {
                const int r = wm * 32 + (ri >> 1) * 16 + g + (ri & 1) * 8;
                s_red[0][r][wn] = dotR[ri];
                s_red[1][r][wn] = n1R[ri];
                s_red[2][r][wn] = n2R[ri];
            }
        }
    }

    // ==================== Phase 3: GEMM3 on tensor cores (1-pass) ===========
    float acc3[2][2][4];
#pragma unroll
    for (int t = 0; t < 2; t++)
#pragma unroll
        for (int u = 0; u < 2; u++)
#pragma unroll
            for (int j = 0; j < 4; j++) acc3[t][u][j] = 0.0f;

    const uint32_t aOff3 = ((wm * 32 + ln16) * ST3 + lhalf * 8) * 2;
    const uint32_t bOff3 = (((wn * 16 + (ln16 & 7)) * ST3) + ((ln16 >> 3) * 8)) * 2;
    char* A3 = Areg;                         // 64*136*2 = 17408 <= 18432
    uint32_t A3U = smem_u32(A3);
    uint32_t B3U = smem_u32(Breg);           // 64*136*2 = 17408 <= 36864

    __syncthreads();   // all warps done with phase-2 stages + s_red written

    for (int f = 0; f < 3; f++) {
        // prefetch W3 chunk f (64 x 128 halves)
#pragma unroll
        for (int it = 0; it < 4; it++) {
            int idx = tid + it * 256;
            int n_ = idx >> 4, cc = idx & 15;
            int off = (n_ * ST3 + cc * 8) * 2;
            cpasync16(B3U + off, g_w3 + n_ * 384 + f * 128 + cc * 8);
        }
        cpasync_commit();

        // write combined feature tile into A region (single fp16, stride ST3)
#pragma unroll
        for (int t = 0; t < 2; t++)
#pragma unroll
            for (int u = 0; u < 4; u++) {
                const int col = wn * 32 + u * 8 + tg * 2;
                const int r   = wm * 32 + t * 16 + g;
                float v[4];
#pragma unroll
                for (int j = 0; j < 4; j++) {
                    const float a = h1[t][u][j];
                    const float b = acc[t][u][j];
                    v[j] = (f == 0) ? a * b : (f == 1) ? fabsf(a - b) : a + b;
                }
                *reinterpret_cast<uint32_t*>(A3 + (r * ST3 + col) * 2)       = pack_h2(v[0], v[1]);
                *reinterpret_cast<uint32_t*>(A3 + ((r + 8) * ST3 + col) * 2) = pack_h2(v[2], v[3]);
            }
        cpasync_wait0();
        __syncthreads();

        // MMA over k=128 (8 steps), single pass
#pragma unroll
        for (int ks = 0; ks < 8; ks++) {
            const uint32_t ko = ks * 32;
            uint32_t Ah[2][4], Bh[2][2];
#pragma unroll
            for (int t = 0; t < 2; t++)
                ldmatrix_x4(Ah[t], A3U + aOff3 + (t * 16 * ST3) * 2 + ko);
#pragma unroll
            for (int u = 0; u < 2; u++)
                ldmatrix_x2(Bh[u], B3U + bOff3 + (u * 8 * ST3) * 2 + ko);
#pragma unroll
            for (int t = 0; t < 2; t++)
#pragma unroll
                for (int u = 0; u < 2; u++)
                    mma_f16(acc3[t][u][0], acc3[t][u][1], acc3[t][u][2], acc3[t][u][3],
                            Ah[t][0], Ah[t][1], Ah[t][2], Ah[t][3],
                            Bh[u][0], Bh[u][1]);
        }
        __syncthreads();
    }

    // ==================== Phase 4: relu -> W4 -> head =======================
    {
        float slR[4];
#pragma unroll
        for (int ri = 0; ri < 4; ri++) slR[ri] = 0.0f;
#pragma unroll
        for (int u = 0; u < 2; u++) {
            const int col = wn * 16 + u * 8 + tg * 2;
            const float b30 = b3[col], b31 = b3[col + 1];
            const float w40 = W4[col], w41 = W4[col + 1];
#pragma unroll
            for (int t = 0; t < 2; t++) {
                slR[t * 2 + 0] += fmaxf(acc3[t][u][0] + b30, 0.0f) * w40
                                + fmaxf(acc3[t][u][1] + b31, 0.0f) * w41;
                slR[t * 2 + 1] += fmaxf(acc3[t][u][2] + b30, 0.0f) * w40
                                + fmaxf(acc3[t][u][3] + b31, 0.0f) * w41;
            }
        }
#pragma unroll
        for (int off = 1; off < 4; off <<= 1)
#pragma unroll
            for (int ri = 0; ri < 4; ri++)
                slR[ri] += __shfl_xor_sync(0xffffffffu, slR[ri], off);
        if (tg == 0) {
#pragma unroll
            for (int ri = 0; ri < 4; ri++) {
                const int r = wm * 32 + (ri >> 1) * 16 + g + (ri & 1) * 8;
                s_red[3][r][wn] = slR[ri];
            }
        }
    }
    __syncthreads();

    if (tid < 64) {
        float dot = 0.f, n1v = 0.f, n2v = 0.f, sl = 0.f;
#pragma unroll
        for (int w = 0; w < 4; w++) {
            dot += s_red[0][tid][w];
            n1v += s_red[1][tid][w];
            n2v += s_red[2][tid][w];
            sl  += s_red[3][tid][w];
        }
        const float inv1   = 1.0f / fmaxf(sqrtf(n1v), 1e-15f);
        const float inv2   = 1.0f / fmaxf(sqrtf(n2v), 1e-15f);
        const float s_math = fminf(fmaxf(dot * inv1 * inv2, 0.0f), 1.0f);
        const float sig    = 1.0f / (1.0f + expf(-(sl + b4[0])));
        const float fin    = alphap[0] * s_math + betap[0] * sig;
        out[row0 + tid] = fminf(fmaxf(fin, 0.0f), 1.0f);
    }
#undef F2_LDA
#undef F2_STA
#undef F2_CPB
}

// ---------------------------------------------------------------------------
extern "C" void kernel_launch(void* const* d_in, const int* in_sizes, int n_in,
                              void* d_out, int out_size)
{
    const float* x1      = (const float*)d_in[0];
    const float* x2      = (const float*)d_in[1];
    const float* W1      = (const float*)d_in[2];
    const float* b1      = (const float*)d_in[3];
    const float* gamma   = (const float*)d_in[4];
    const float* beta_bn = (const float*)d_in[5];
    const float* W2      = (const float*)d_in[6];
    const float* b2      = (const float*)d_in[7];
    const float* W3      = (const float*)d_in[8];
    const float* b3      = (const float*)d_in[9];
    const float* W4      = (const float*)d_in[10];
    const float* b4      = (const float*)d_in[11];
    const float* alphap  = (const float*)d_in[12];
    const float* betap   = (const float*)d_in[13];
    float* out = (float*)d_out;

    cudaFuncSetAttribute(gemm1_mma,
                         cudaFuncAttributeMaxDynamicSharedMemorySize, G1_DYN);
    cudaFuncSetAttribute(fused2,
                         cudaFuncAttributeMaxDynamicSharedMemorySize, F2_DYN);

    const int prep_elems = DK * HH + HH * H2 + 384 * O3;
    prep_weights<<<(prep_elems + 255) / 256, 256>>>(W1, W2, W3);

    dim3 g1(NRB1, 2);
    gemm1_mma<<<g1, 256, G1_DYN>>>(x1, x2, b1);

    stats_kernel<<<512, 256>>>(gamma, beta_bn);

    fused2<<<NRB2, 256, F2_DYN>>>(b2, b3, W4, b4, alphap, betap, out);
}

// round 13
// speedup vs baseline: 1.0232x; 1.0232x over previous
#include <cuda_runtime.h>
#include <cuda_bf16.h>
#include <cuda_fp16.h>
#include <cstdint>
#include <math.h>

// ---------------------------------------------------------------------------
// Problem constants
// ---------------------------------------------------------------------------
#define NROWS 65536
#define DK    512
#define HH    256
#define H2    128
#define O3    64
#define NRB1  1024          // gemm1 row blocks of 64
#define NRB2  1024          // fused2 row blocks of 64

// ---------------------------------------------------------------------------
// Scratch (device globals — allocation-free per harness rules)
// ---------------------------------------------------------------------------
__device__ __align__(16) __half g_hraw[2 * NROWS * HH];   // 64 MB fp16 pre-BN
__device__ float g_psum[2 * NRB1 * HH];
__device__ float g_psq [2 * NRB1 * HH];
__device__ float g_scale[2 * HH];
__device__ float g_shift[2 * HH];
// All weights single fp16, transposed K-major [N][K]
__device__ __align__(16) __half g_w1[HH * DK];
__device__ __align__(16) __half g_w2[H2 * HH];
__device__ __align__(16) __half g_w3[O3 * 384];

// ---------------------------------------------------------------------------
// Warp-MMA helpers (base PTX — no sm_103a-only features)
// ---------------------------------------------------------------------------
__device__ __forceinline__ uint32_t smem_u32(const void* p) {
    uint32_t a;
    asm("{ .reg .u64 t; cvta.to.shared.u64 t, %1; cvt.u32.u64 %0, t; }"
        : "=r"(a) : "l"(p));
    return a;
}

__device__ __forceinline__ void mma_f16(float& c0, float& c1, float& c2, float& c3,
                                        uint32_t a0, uint32_t a1, uint32_t a2, uint32_t a3,
                                        uint32_t b0, uint32_t b1) {
    asm volatile(
        "mma.sync.aligned.m16n8k16.row.col.f32.f16.f16.f32 "
        "{%0,%1,%2,%3}, {%4,%5,%6,%7}, {%8,%9}, {%0,%1,%2,%3};"
        : "+f"(c0), "+f"(c1), "+f"(c2), "+f"(c3)
        : "r"(a0), "r"(a1), "r"(a2), "r"(a3), "r"(b0), "r"(b1));
}

__device__ __forceinline__ void ldmatrix_x4(uint32_t* r, uint32_t addr) {
    asm volatile("ldmatrix.sync.aligned.m8n8.x4.shared.b16 {%0,%1,%2,%3}, [%4];"
        : "=r"(r[0]), "=r"(r[1]), "=r"(r[2]), "=r"(r[3]) : "r"(addr));
}

__device__ __forceinline__ void ldmatrix_x2(uint32_t* r, uint32_t addr) {
    asm volatile("ldmatrix.sync.aligned.m8n8.x2.shared.b16 {%0,%1}, [%2];"
        : "=r"(r[0]), "=r"(r[1]) : "r"(addr));
}

__device__ __forceinline__ void cpasync16(uint32_t dst, const void* src) {
    asm volatile("cp.async.cg.shared.global [%0], [%1], 16;" :: "r"(dst), "l"(src));
}
__device__ __forceinline__ void cpasync_commit() {
    asm volatile("cp.async.commit_group;" ::: "memory");
}
__device__ __forceinline__ void cpasync_wait0() {
    asm volatile("cp.async.wait_group 0;" ::: "memory");
}

// pack (x,y) into one fp16x2 word
__device__ __forceinline__ uint32_t pack_h2(float x, float y) {
    __half2 h = __floats2half2_rn(x, y);
    return *reinterpret_cast<uint32_t*>(&h);
}

__device__ __forceinline__ float2 unpack_h2(uint32_t u) {
    __half2 h = *reinterpret_cast<__half2*>(&u);
    return __half22float2(h);
}

// ---------------------------------------------------------------------------
// Weight prep: transpose to K-major fp16. W1[256][512], W2[128][256], W3[64][384].
// ---------------------------------------------------------------------------
__global__ void prep_weights(const float* __restrict__ W1,
                             const float* __restrict__ W2,
                             const float* __restrict__ W3)
{
    int i = blockIdx.x * 256 + threadIdx.x;
    if (i < DK * HH) {
        int k = i >> 8, n = i & 255;
        g_w1[n * DK + k] = __float2half_rn(W1[i]);
        return;
    }
    int j = i - DK * HH;
    if (j < HH * H2) {
        int k = j >> 7, n = j & 127;
        g_w2[n * HH + k] = __float2half_rn(W2[j]);
        return;
    }
    int j2 = j - HH * H2;
    if (j2 < 384 * O3) {
        int k = j2 >> 6, n = j2 & 63;
        g_w3[n * 384 + k] = __float2half_rn(W3[j2]);
    }
}

// ---------------------------------------------------------------------------
// GEMM1 (Round-10 proven config): hraw(fp16) = X @ W1 + b1, plus stats.
// CTA 64x256, 256 threads, 8 warps (1m x 8n), warp tile 64x32.
// 92 KB smem -> 2 CTAs/SM.
// ---------------------------------------------------------------------------
#define AST 72
#define G1_AB  (64 * AST * 2)                 // 9216
#define G1_BB  (256 * AST * 2)                // 36864
#define G1_STAGE (G1_AB + G1_BB)              // 46080
#define G1_DYN   (2 * G1_STAGE)               // 92160

__global__ void __launch_bounds__(256) gemm1_mma(
    const float* __restrict__ x1, const float* __restrict__ x2,
    const float* __restrict__ b1)
{
    extern __shared__ char dyn[];
    const int z    = blockIdx.y;
    const int rb   = blockIdx.x;
    const int row0 = rb * 64;
    const float* __restrict__ X = z ? x2 : x1;

    const int tid  = threadIdx.x;
    const int lane = tid & 31;
    const int wn   = tid >> 5;       // warp id = n-tile 0..7
    const int g    = lane >> 2;      // 0..7
    const int tg   = lane & 3;       // 0..3
    const int ln16 = lane & 15;
    const int lhalf = (lane >> 4) & 1;

    float acc[4][4][4];
#pragma unroll
    for (int t = 0; t < 4; t++)
#pragma unroll
        for (int u = 0; u < 4; u++)
#pragma unroll
            for (int j = 0; j < 4; j++) acc[t][u][j] = 0.0f;

    float4 aNext[4];

#define G1_LDA(c) do { \
        const int kk_ = (c) * 64; \
        _Pragma("unroll") \
        for (int it = 0; it < 4; it++) { \
            int idx = tid + it * 256; \
            int r_  = idx >> 4, c4_ = idx & 15; \
            aNext[it] = *reinterpret_cast<const float4*>( \
                X + (size_t)(row0 + r_) * DK + kk_ + c4_ * 4); \
        } \
    } while (0)

#define G1_STA(stg) do { \
        char* sAh_ = dyn + (stg) * G1_STAGE; \
        _Pragma("unroll") \
        for (int it = 0; it < 4; it++) { \
            int idx = tid + it * 256; \
            int r_  = idx >> 4, c4_ = idx & 15; \
            uint32_t p0 = pack_h2(aNext[it].x, aNext[it].y); \
            uint32_t p1 = pack_h2(aNext[it].z, aNext[it].w); \
            int off = (r_ * AST + c4_ * 4) * 2; \
            *reinterpret_cast<uint2*>(sAh_ + off) = make_uint2(p0, p1); \
        } \
    } while (0)

#define G1_CPB(c, stg) do { \
        const int kk_ = (c) * 64; \
        char* sB_ = dyn + (stg) * G1_STAGE + G1_AB; \
        uint32_t bU = smem_u32(sB_); \
        _Pragma("unroll") \
        for (int it = 0; it < 8; it++) { \
            int idx = tid + it * 256; \
            int n_ = idx >> 3, c8_ = idx & 7; \
            int off = (n_ * AST + c8_ * 8) * 2; \
            cpasync16(bU + off, g_w1 + (size_t)n_ * DK + kk_ + c8_ * 8); \
        } \
        cpasync_commit(); \
    } while (0)

    G1_CPB(0, 0);
    G1_LDA(0);
    G1_STA(0);
    cpasync_wait0();
    __syncthreads();

    const int NC = DK / 64;   // 8
    for (int c = 0; c < NC; c++) {
        const int s = c & 1;
        if (c + 1 < NC) {
            G1_CPB(c + 1, s ^ 1);
            G1_LDA(c + 1);
        }

        {
            char* st = dyn + s * G1_STAGE;
            uint32_t sAhU = smem_u32(st);
            uint32_t sBU  = sAhU + G1_AB;

            const uint32_t aOff = (ln16 * AST + lhalf * 8) * 2;
            const uint32_t bOff = (((wn * 32 + (ln16 & 7)) * AST) + ((ln16 >> 3) * 8)) * 2;

#pragma unroll
            for (int ks = 0; ks < 4; ks++) {
                const uint32_t ko = ks * 32;
                uint32_t Ah[4][4], Bh[4][2];
#pragma unroll
                for (int t = 0; t < 4; t++)
                    ldmatrix_x4(Ah[t], sAhU + aOff + (t * 16 * AST) * 2 + ko);
#pragma unroll
                for (int u = 0; u < 4; u++)
                    ldmatrix_x2(Bh[u], sBU + bOff + (u * 8 * AST) * 2 + ko);
#pragma unroll
                for (int t = 0; t < 4; t++)
#pragma unroll
                    for (int u = 0; u < 4; u++)
                        mma_f16(acc[t][u][0], acc[t][u][1], acc[t][u][2], acc[t][u][3],
                                Ah[t][0], Ah[t][1], Ah[t][2], Ah[t][3],
                                Bh[u][0], Bh[u][1]);
            }
        }

        if (c + 1 < NC) {
            G1_STA(s ^ 1);
            cpasync_wait0();
            __syncthreads();
        }
    }

    // ---- epilogue: bias, store hraw (fp16), column partial stats ----
    float css0[4], css1[4], cqq0[4], cqq1[4];
#pragma unroll
    for (int u = 0; u < 4; u++) {
        const int col = wn * 32 + u * 8 + tg * 2;
        const float bi0 = b1[col], bi1 = b1[col + 1];
        float cs0 = 0.f, cs1 = 0.f, cq0 = 0.f, cq1 = 0.f;
#pragma unroll
        for (int t = 0; t < 4; t++) {
            const int r = row0 + t * 16 + g;
            float v0 = acc[t][u][0] + bi0;
            float v1 = acc[t][u][1] + bi1;
            float v2 = acc[t][u][2] + bi0;
            float v3 = acc[t][u][3] + bi1;
            *reinterpret_cast<uint32_t*>(
                &g_hraw[((size_t)z * NROWS + r) * HH + col])     = pack_h2(v0, v1);
            *reinterpret_cast<uint32_t*>(
                &g_hraw[((size_t)z * NROWS + r + 8) * HH + col]) = pack_h2(v2, v3);
            cs0 += v0 + v2; cs1 += v1 + v3;
            cq0 += v0 * v0 + v2 * v2; cq1 += v1 * v1 + v3 * v3;
        }
        css0[u] = cs0; css1[u] = cs1; cqq0[u] = cq0; cqq1[u] = cq1;
    }
#pragma unroll
    for (int off = 4; off < 32; off <<= 1) {
#pragma unroll
        for (int u = 0; u < 4; u++) {
            css0[u] += __shfl_xor_sync(0xffffffffu, css0[u], off);
            css1[u] += __shfl_xor_sync(0xffffffffu, css1[u], off);
            cqq0[u] += __shfl_xor_sync(0xffffffffu, cqq0[u], off);
            cqq1[u] += __shfl_xor_sync(0xffffffffu, cqq1[u], off);
        }
    }
    if (g == 0) {
#pragma unroll
        for (int u = 0; u < 4; u++) {
            const int col = wn * 32 + u * 8 + tg * 2;
            const size_t base = ((size_t)z * NRB1 + rb) * HH + col;
            g_psum[base]     = css0[u];
            g_psum[base + 1] = css1[u];
            g_psq [base]     = cqq0[u];
            g_psq [base + 1] = cqq1[u];
        }
    }
#undef G1_LDA
#undef G1_STA
#undef G1_CPB
}

// ---------------------------------------------------------------------------
// Stats: one block per (z, column); 256 threads reduce NRB1 partials.
// ---------------------------------------------------------------------------
__global__ void __launch_bounds__(256) stats_kernel(
    const float* __restrict__ gamma, const float* __restrict__ beta_bn)
{
    const int z = blockIdx.x >> 8;
    const int c = blockIdx.x & 255;
    const int tid = threadIdx.x;

    float s = 0.0f, q = 0.0f;
    for (int i = tid; i < NRB1; i += 256) {
        s += g_psum[((size_t)z * NRB1 + i) * HH + c];
        q += g_psq [((size_t)z * NRB1 + i) * HH + c];
    }
#pragma unroll
    for (int off = 16; off > 0; off >>= 1) {
        s += __shfl_xor_sync(0xffffffffu, s, off);
        q += __shfl_xor_sync(0xffffffffu, q, off);
    }
    __shared__ float rs[8], rq[8];
    if ((tid & 31) == 0) { rs[tid >> 5] = s; rq[tid >> 5] = q; }
    __syncthreads();
    if (tid == 0) {
        float S = 0.f, Q = 0.f;
#pragma unroll
        for (int w = 0; w < 8; w++) { S += rs[w]; Q += rq[w]; }
        const float mean = S / (float)NROWS;
        const float var  = Q / (float)NROWS - mean * mean;
        const float sc   = gamma[c] * rsqrtf(var + 1e-5f);
        g_scale[z * HH + c] = sc;
        g_shift[z * HH + c] = beta_bn[c] - mean * sc;
    }
}

// ---------------------------------------------------------------------------
// FUSED v4 (Round-11 proven config): 64-row CTAs, 2 CTAs/SM.
// 8 warps (2m x 4n): GEMM2 warp tile 32x32, GEMM3 warp tile 32x16.
// ---------------------------------------------------------------------------
#define F2_AB   (64 * AST * 2)         // 9216 (single A stage)
#define F2_AREG (2 * F2_AB)            // 18432
#define F2_BB   (128 * AST * 2)        // 18432
#define F2_BREG (2 * F2_BB)            // 36864
#define F2_DYN  (F2_AREG + F2_BREG)    // 55296
#define ST3 136

__global__ void __launch_bounds__(256, 2) fused2(
    const float* __restrict__ b2, const float* __restrict__ b3,
    const float* __restrict__ W4, const float* __restrict__ b4,
    const float* __restrict__ alphap, const float* __restrict__ betap,
    float* __restrict__ out)
{
    extern __shared__ char dyn[];
    __shared__ float s_sc[HH];
    __shared__ float s_sh[HH];
    __shared__ float s_red[4][64][4];

    const int rb   = blockIdx.x;
    const int row0 = rb * 64;
    const int tid  = threadIdx.x;
    const int lane = tid & 31;
    const int wid  = tid >> 5;
    const int wm   = wid >> 2;       // 0..1
    const int wn   = wid & 3;        // 0..3
    const int g    = lane >> 2;
    const int tg   = lane & 3;
    const int ln16 = lane & 15;
    const int lhalf = (lane >> 4) & 1;

    char* Areg = dyn;
    char* Breg = dyn + F2_AREG;

    float acc[2][4][4];
    float h1[2][4][4];
    uint4 aNext[2];

    const uint32_t aOff2 = ((wm * 32 + ln16) * AST + lhalf * 8) * 2;
    const uint32_t bOff2 = (((wn * 32 + (ln16 & 7)) * AST) + ((ln16 >> 3) * 8)) * 2;

#define F2_LDA(zz, c) do { \
        const int kk_ = (c) * 64; \
        _Pragma("unroll") \
        for (int it = 0; it < 2; it++) { \
            int idx = tid + it * 256; \
            int r_  = idx >> 3, c8_ = idx & 7; \
            aNext[it] = *reinterpret_cast<const uint4*>( \
                g_hraw + ((size_t)(zz) * NROWS + row0 + r_) * HH + kk_ + c8_ * 8); \
        } \
    } while (0)

#define F2_STA(c, stg) do { \
        const int kk_ = (c) * 64; \
        char* sA_ = Areg + (stg) * F2_AB; \
        _Pragma("unroll") \
        for (int it = 0; it < 2; it++) { \
            int idx = tid + it * 256; \
            int r_  = idx >> 3, c8_ = idx & 7; \
            const int col_ = kk_ + c8_ * 8; \
            float2 f0 = unpack_h2(aNext[it].x); \
            float2 f1 = unpack_h2(aNext[it].y); \
            float2 f2 = unpack_h2(aNext[it].z); \
            float2 f3 = unpack_h2(aNext[it].w); \
            float a0 = fmaxf(s_sc[col_ + 0] * f0.x + s_sh[col_ + 0], 0.0f); \
            float a1 = fmaxf(s_sc[col_ + 1] * f0.y + s_sh[col_ + 1], 0.0f); \
            float a2 = fmaxf(s_sc[col_ + 2] * f1.x + s_sh[col_ + 2], 0.0f); \
            float a3 = fmaxf(s_sc[col_ + 3] * f1.y + s_sh[col_ + 3], 0.0f); \
            float a4 = fmaxf(s_sc[col_ + 4] * f2.x + s_sh[col_ + 4], 0.0f); \
            float a5 = fmaxf(s_sc[col_ + 5] * f2.y + s_sh[col_ + 5], 0.0f); \
            float a6 = fmaxf(s_sc[col_ + 6] * f3.x + s_sh[col_ + 6], 0.0f); \
            float a7 = fmaxf(s_sc[col_ + 7] * f3.y + s_sh[col_ + 7], 0.0f); \
            int off = (r_ * AST + c8_ * 8) * 2; \
            *reinterpret_cast<uint4*>(sA_ + off) = \
                make_uint4(pack_h2(a0, a1), pack_h2(a2, a3), \
                           pack_h2(a4, a5), pack_h2(a6, a7)); \
        } \
    } while (0)

#define F2_CPB(c, stg) do { \
        const int kk_ = (c) * 64; \
        char* sB_ = Breg + (stg) * F2_BB; \
        uint32_t bU = smem_u32(sB_); \
        _Pragma("unroll") \
        for (int it = 0; it < 4; it++) { \
            int idx = tid + it * 256; \
            int n_ = idx >> 3, c8_ = idx & 7; \
            int off = (n_ * AST + c8_ * 8) * 2; \
            cpasync16(bU + off, g_w2 + (size_t)n_ * HH + kk_ + c8_ * 8); \
        } \
        cpasync_commit(); \
    } while (0)

    // ========================= Phases 1 & 2: GEMM2 x2 =======================
    for (int z = 0; z < 2; z++) {
        __syncthreads();
        s_sc[tid] = g_scale[z * HH + tid];
        s_sh[tid] = g_shift[z * HH + tid];
        __syncthreads();

#pragma unroll
        for (int t = 0; t < 2; t++)
#pragma unroll
            for (int u = 0; u < 4; u++)
#pragma unroll
                for (int j = 0; j < 4; j++) acc[t][u][j] = 0.0f;

        F2_CPB(0, 0);
        F2_LDA(z, 0);
        F2_STA(0, 0);
        cpasync_wait0();
        __syncthreads();

        const int NC = 4;
        for (int c = 0; c < NC; c++) {
            const int s = c & 1;
            if (c + 1 < NC) {
                F2_CPB(c + 1, s ^ 1);
                F2_LDA(z, c + 1);
            }
            {
                uint32_t sAU = smem_u32(Areg + s * F2_AB);
                uint32_t sBU = smem_u32(Breg + s * F2_BB);
#pragma unroll
                for (int ks = 0; ks < 4; ks++) {
                    const uint32_t ko = ks * 32;
                    uint32_t Ah[2][4], Bh[4][2];
#pragma unroll
                    for (int t = 0; t < 2; t++)
                        ldmatrix_x4(Ah[t], sAU + aOff2 + (t * 16 * AST) * 2 + ko);
#pragma unroll
                    for (int u = 0; u < 4; u++)
                        ldmatrix_x2(Bh[u], sBU + bOff2 + (u * 8 * AST) * 2 + ko);
#pragma unroll
                    for (int t = 0; t < 2; t++)
#pragma unroll
                        for (int u = 0; u < 4; u++)
                            mma_f16(acc[t][u][0], acc[t][u][1], acc[t][u][2], acc[t][u][3],
                                    Ah[t][0], Ah[t][1], Ah[t][2], Ah[t][3],
                                    Bh[u][0], Bh[u][1]);
                }
            }
            if (c + 1 < NC) {
                __syncthreads();
                F2_STA(c + 1, s ^ 1);
                cpasync_wait0();
                __syncthreads();
            }
        }

        // epilogue: h = relu(acc + b2); stash into h1 (z=0) or keep in acc (z=1)
#pragma unroll
        for (int u = 0; u < 4; u++) {
            const int col = wn * 32 + u * 8 + tg * 2;
            const float bi0 = b2[col], bi1 = b2[col + 1];
#pragma unroll
            for (int t = 0; t < 2; t++) {
                float v0 = fmaxf(acc[t][u][0] + bi0, 0.0f);
                float v1 = fmaxf(acc[t][u][1] + bi1, 0.0f);
                float v2 = fmaxf(acc[t][u][2] + bi0, 0.0f);
                float v3 = fmaxf(acc[t][u][3] + bi1, 0.0f);
                if (z == 0) {
                    h1[t][u][0] = v0; h1[t][u][1] = v1;
                    h1[t][u][2] = v2; h1[t][u][3] = v3;
                } else {
                    acc[t][u][0] = v0; acc[t][u][1] = v1;
                    acc[t][u][2] = v2; acc[t][u][3] = v3;
                }
            }
        }
    }

    // ================== cosine partials (row-wise) from fragments ==========
    {
        float dotR[4], n1R[4], n2R[4];
#pragma unroll
        for (int ri = 0; ri < 4; ri++) { dotR[ri] = 0.f; n1R[ri] = 0.f; n2R[ri] = 0.f; }
#pragma unroll
        for (int t = 0; t < 2; t++)
#pragma unroll
            for (int u = 0; u < 4; u++)
#pragma unroll
                for (int j = 0; j < 4; j++) {
                    const float a = h1[t][u][j];
                    const float b = acc[t][u][j];
                    const int ri = t * 2 + (j >> 1);
                    dotR[ri] = fmaf(a, b, dotR[ri]);
                    n1R[ri]  = fmaf(a, a, n1R[ri]);
                    n2R[ri]  = fmaf(b, b, n2R[ri]);
                }
#pragma unroll
        for (int off = 1; off < 4; off <<= 1) {
#pragma unroll
            for (int ri = 0; ri < 4; ri++) {
                dotR[ri] += __shfl_xor_sync(0xffffffffu, dotR[ri], off);
                n1R[ri]  += __shfl_xor_sync(0xffffffffu, n1R[ri], off);
                n2R[ri]  += __shfl_xor_sync(0xffffffffu, n2R[ri], off);
            }
        }
        if (tg == 0) {
#pragma unroll
            for (int ri = 0; ri < 4; ri++) {
                const int r = wm * 32 + (ri >> 1) * 16 + g + (ri & 1) * 8;
                s_red[0][r][wn] = dotR[ri];
                s_red[1][r][wn] = n1R[ri];
                s_red[2][r][wn] = n2R[ri];
            }
        }
    }

    // ==================== Phase 3: GEMM3 on tensor cores (1-pass) ===========
    float acc3[2][2][4];
#pragma unroll
    for (int t = 0; t < 2; t++)
#pragma unroll
        for (int u = 0; u < 2; u++)
#pragma unroll
            for (int j = 0; j < 4; j++) acc3[t][u][j] = 0.0f;

    const uint32_t aOff3 = ((wm * 32 + ln16) * ST3 + lhalf * 8) * 2;
    const uint32_t bOff3 = (((wn * 16 + (ln16 & 7)) * ST3) + ((ln16 >> 3) * 8)) * 2;
    char* A3 = Areg;                         // 64*136*2 = 17408 <= 18432
    uint32_t A3U = smem_u32(A3);
    uint32_t B3U = smem_u32(Breg);           // 64*136*2 = 17408 <= 36864

    __syncthreads();   // all warps done with phase-2 stages + s_red written

    for (int f = 0; f < 3; f++) {
        // prefetch W3 chunk f (64 x 128 halves)
#pragma unroll
        for (int it = 0; it < 4; it++) {
            int idx = tid + it * 256;
            int n_ = idx >> 4, cc = idx & 15;
            int off = (n_ * ST3 + cc * 8) * 2;
            cpasync16(B3U + off, g_w3 + n_ * 384 + f * 128 + cc * 8);
        }
        cpasync_commit();

        // write combined feature tile into A region (single fp16, stride ST3)
#pragma unroll
        for (int t = 0; t < 2; t++)
#pragma unroll
            for (int u = 0; u < 4; u++) {
                const int col = wn * 32 + u * 8 + tg * 2;
                const int r   = wm * 32 + t * 16 + g;
                float v[4];
#pragma unroll
                for (int j = 0; j < 4; j++) {
                    const float a = h1[t][u][j];
                    const float b = acc[t][u][j];
                    v[j] = (f == 0) ? a * b : (f == 1) ? fabsf(a - b) : a + b;
                }
                *reinterpret_cast<uint32_t*>(A3 + (r * ST3 + col) * 2)       = pack_h2(v[0], v[1]);
                *reinterpret_cast<uint32_t*>(A3 + ((r + 8) * ST3 + col) * 2) = pack_h2(v[2], v[3]);
            }
        cpasync_wait0();
        __syncthreads();

        // MMA over k=128 (8 steps), single pass
#pragma unroll
        for (int ks = 0; ks < 8; ks++) {
            const uint32_t ko = ks * 32;
            uint32_t Ah[2][4], Bh[2][2];
#pragma unroll
            for (int t = 0; t < 2; t++)
                ldmatrix_x4(Ah[t], A3U + aOff3 + (t * 16 * ST3) * 2 + ko);
#pragma unroll
            for (int u = 0; u < 2; u++)
                ldmatrix_x2(Bh[u], B3U + bOff3 + (u * 8 * ST3) * 2 + ko);
#pragma unroll
            for (int t = 0; t < 2; t++)
#pragma unroll
                for (int u = 0; u < 2; u++)
                    mma_f16(acc3[t][u][0], acc3[t][u][1], acc3[t][u][2], acc3[t][u][3],
                            Ah[t][0], Ah[t][1], Ah[t][2], Ah[t][3],
                            Bh[u][0], Bh[u][1]);
        }
        __syncthreads();
    }

    // ==================== Phase 4: relu -> W4 -> head =======================
    {
        float slR[4];
#pragma unroll
        for (int ri = 0; ri < 4; ri++) slR[ri] = 0.0f;
#pragma unroll
        for (int u = 0; u < 2; u++) {
            const int col = wn * 16 + u * 8 + tg * 2;
            const float b30 = b3[col], b31 = b3[col + 1];
            const float w40 = W4[col], w41 = W4[col + 1];
#pragma unroll
            for (int t = 0; t < 2; t++) {
                slR[t * 2 + 0] += fmaxf(acc3[t][u][0] + b30, 0.0f) * w40
                                + fmaxf(acc3[t][u][1] + b31, 0.0f) * w41;
                slR[t * 2 + 1] += fmaxf(acc3[t][u][2] + b30, 0.0f) * w40
                                + fmaxf(acc3[t][u][3] + b31, 0.0f) * w41;
            }
        }
#pragma unroll
        for (int off = 1; off < 4; off <<= 1)
#pragma unroll
            for (int ri = 0; ri < 4; ri++)
                slR[ri] += __shfl_xor_sync(0xffffffffu, slR[ri], off);
        if (tg == 0) {
#pragma unroll
            for (int ri = 0; ri < 4; ri++) {
                const int r = wm * 32 + (ri >> 1) * 16 + g + (ri & 1) * 8;
                s_red[3][r][wn] = slR[ri];
            }
        }
    }
    __syncthreads();

    if (tid < 64) {
        float dot = 0.f, n1v = 0.f, n2v = 0.f, sl = 0.f;
#pragma unroll
        for (int w = 0; w < 4; w++) {
            dot += s_red[0][tid][w];
            n1v += s_red[1][tid][w];
            n2v += s_red[2][tid][w];
            sl  += s_red[3][tid][w];
        }
        const float inv1   = 1.0f / fmaxf(sqrtf(n1v), 1e-15f);
        const float inv2   = 1.0f / fmaxf(sqrtf(n2v), 1e-15f);
        const float s_math = fminf(fmaxf(dot * inv1 * inv2, 0.0f), 1.0f);
        const float sig    = 1.0f / (1.0f + expf(-(sl + b4[0])));
        const float fin    = alphap[0] * s_math + betap[0] * sig;
        out[row0 + tid] = fminf(fmaxf(fin, 0.0f), 1.0f);
    }
#undef F2_LDA
#undef F2_STA
#undef F2_CPB
}

// ---------------------------------------------------------------------------
extern "C" void kernel_launch(void* const* d_in, const int* in_sizes, int n_in,
                              void* d_out, int out_size)
{
    const float* x1      = (const float*)d_in[0];
    const float* x2      = (const float*)d_in[1];
    const float* W1      = (const float*)d_in[2];
    const float* b1      = (const float*)d_in[3];
    const float* gamma   = (const float*)d_in[4];
    const float* beta_bn = (const float*)d_in[5];
    const float* W2      = (const float*)d_in[6];
    const float* b2      = (const float*)d_in[7];
    const float* W3      = (const float*)d_in[8];
    const float* b3      = (const float*)d_in[9];
    const float* W4      = (const float*)d_in[10];
    const float* b4      = (const float*)d_in[11];
    const float* alphap  = (const float*)d_in[12];
    const float* betap   = (const float*)d_in[13];
    float* out = (float*)d_out;

    cudaFuncSetAttribute(gemm1_mma,
                         cudaFuncAttributeMaxDynamicSharedMemorySize, G1_DYN);
    cudaFuncSetAttribute(fused2,
                         cudaFuncAttributeMaxDynamicSharedMemorySize, F2_DYN);

    const int prep_elems = DK * HH + HH * H2 + 384 * O3;
    prep_weights<<<(prep_elems + 255) / 256, 256>>>(W1, W2, W3);

    dim3 g1(NRB1, 2);
    gemm1_mma<<<g1, 256, G1_DYN>>>(x1, x2, b1);

    stats_kernel<<<512, 256>>>(gamma, beta_bn);

    fused2<<<NRB2, 256, F2_DYN>>>(b2, b3, W4, b4, alphap, betap, out);
}

// round 14
// speedup vs baseline: 1.0292x; 1.0059x over previous
#include <cuda_runtime.h>
#include <cuda_bf16.h>
#include <cuda_fp16.h>
#include <cstdint>
#include <math.h>

// ---------------------------------------------------------------------------
// Problem constants
// ---------------------------------------------------------------------------
#define NROWS 65536
#define DK    512
#define HH    256
#define H2    128
#define O3    64
#define NRB1  1024          // gemm1 row blocks of 64
#define NRB2  1024          // fused2 row blocks of 64

// ---------------------------------------------------------------------------
// Scratch (device globals — allocation-free per harness rules)
// ---------------------------------------------------------------------------
__device__ __align__(16) __half g_hraw[2 * NROWS * HH];   // 64 MB fp16 pre-BN
__device__ float g_psum[2 * NRB1 * HH];
__device__ float g_psq [2 * NRB1 * HH];
__device__ float g_scale[2 * HH];
__device__ float g_shift[2 * HH];
// All weights single fp16, transposed K-major [N][K]
__device__ __align__(16) __half g_w1[HH * DK];
__device__ __align__(16) __half g_w2[H2 * HH];
__device__ __align__(16) __half g_w3[O3 * 384];

// ---------------------------------------------------------------------------
// Warp-MMA helpers (base PTX — no sm_103a-only features)
// ---------------------------------------------------------------------------
__device__ __forceinline__ uint32_t smem_u32(const void* p) {
    uint32_t a;
    asm("{ .reg .u64 t; cvta.to.shared.u64 t, %1; cvt.u32.u64 %0, t; }"
        : "=r"(a) : "l"(p));
    return a;
}

__device__ __forceinline__ void mma_f16(float& c0, float& c1, float& c2, float& c3,
                                        uint32_t a0, uint32_t a1, uint32_t a2, uint32_t a3,
                                        uint32_t b0, uint32_t b1) {
    asm volatile(
        "mma.sync.aligned.m16n8k16.row.col.f32.f16.f16.f32 "
        "{%0,%1,%2,%3}, {%4,%5,%6,%7}, {%8,%9}, {%0,%1,%2,%3};"
        : "+f"(c0), "+f"(c1), "+f"(c2), "+f"(c3)
        : "r"(a0), "r"(a1), "r"(a2), "r"(a3), "r"(b0), "r"(b1));
}

__device__ __forceinline__ void ldmatrix_x4(uint32_t* r, uint32_t addr) {
    asm volatile("ldmatrix.sync.aligned.m8n8.x4.shared.b16 {%0,%1,%2,%3}, [%4];"
        : "=r"(r[0]), "=r"(r[1]), "=r"(r[2]), "=r"(r[3]) : "r"(addr));
}

__device__ __forceinline__ void cpasync16(uint32_t dst, const void* src) {
    asm volatile("cp.async.cg.shared.global [%0], [%1], 16;" :: "r"(dst), "l"(src));
}
__device__ __forceinline__ void cpasync_commit() {
    asm volatile("cp.async.commit_group;" ::: "memory");
}
__device__ __forceinline__ void cpasync_wait0() {
    asm volatile("cp.async.wait_group 0;" ::: "memory");
}

// pack (x,y) into one fp16x2 word
__device__ __forceinline__ uint32_t pack_h2(float x, float y) {
    __half2 h = __floats2half2_rn(x, y);
    return *reinterpret_cast<uint32_t*>(&h);
}

__device__ __forceinline__ float2 unpack_h2(uint32_t u) {
    __half2 h = *reinterpret_cast<__half2*>(&u);
    return __half22float2(h);
}

// ---------------------------------------------------------------------------
// Weight prep: transpose to K-major fp16. W1[256][512], W2[128][256], W3[64][384].
// ---------------------------------------------------------------------------
__global__ void prep_weights(const float* __restrict__ W1,
                             const float* __restrict__ W2,
                             const float* __restrict__ W3)
{
    int i = blockIdx.x * 256 + threadIdx.x;
    if (i < DK * HH) {
        int k = i >> 8, n = i & 255;
        g_w1[n * DK + k] = __float2half_rn(W1[i]);
        return;
    }
    int j = i - DK * HH;
    if (j < HH * H2) {
        int k = j >> 7, n = j & 127;
        g_w2[n * HH + k] = __float2half_rn(W2[j]);
        return;
    }
    int j2 = j - HH * H2;
    if (j2 < 384 * O3) {
        int k = j2 >> 6, n = j2 & 63;
        g_w3[n * 384 + k] = __float2half_rn(W3[j2]);
    }
}

// ---------------------------------------------------------------------------
// GEMM1: hraw(fp16) = X @ W1 + b1, plus stats.
// CTA 64x256, 256 threads, 8 warps (1m x 8n), warp tile 64x32.
// B fragments loaded pairwise via ldmatrix.x4 (all 32 lanes active).
// ---------------------------------------------------------------------------
#define AST 72
#define G1_AB  (64 * AST * 2)                 // 9216
#define G1_BB  (256 * AST * 2)                // 36864
#define G1_STAGE (G1_AB + G1_BB)              // 46080
#define G1_DYN   (2 * G1_STAGE)               // 92160

__global__ void __launch_bounds__(256) gemm1_mma(
    const float* __restrict__ x1, const float* __restrict__ x2,
    const float* __restrict__ b1)
{
    extern __shared__ char dyn[];
    const int z    = blockIdx.y;
    const int rb   = blockIdx.x;
    const int row0 = rb * 64;
    const float* __restrict__ X = z ? x2 : x1;

    const int tid  = threadIdx.x;
    const int lane = tid & 31;
    const int wn   = tid >> 5;       // warp id = n-tile 0..7
    const int g    = lane >> 2;      // 0..7
    const int tg   = lane & 3;       // 0..3
    const int ln16 = lane & 15;
    const int lhalf = (lane >> 4) & 1;

    float acc[4][4][4];
#pragma unroll
    for (int t = 0; t < 4; t++)
#pragma unroll
        for (int u = 0; u < 4; u++)
#pragma unroll
            for (int j = 0; j < 4; j++) acc[t][u][j] = 0.0f;

    float4 aNext[4];

#define G1_LDA(c) do { \
        const int kk_ = (c) * 64; \
        _Pragma("unroll") \
        for (int it = 0; it < 4; it++) { \
            int idx = tid + it * 256; \
            int r_  = idx >> 4, c4_ = idx & 15; \
            aNext[it] = *reinterpret_cast<const float4*>( \
                X + (size_t)(row0 + r_) * DK + kk_ + c4_ * 4); \
        } \
    } while (0)

#define G1_STA(stg) do { \
        char* sAh_ = dyn + (stg) * G1_STAGE; \
        _Pragma("unroll") \
        for (int it = 0; it < 4; it++) { \
            int idx = tid + it * 256; \
            int r_  = idx >> 4, c4_ = idx & 15; \
            uint32_t p0 = pack_h2(aNext[it].x, aNext[it].y); \
            uint32_t p1 = pack_h2(aNext[it].z, aNext[it].w); \
            int off = (r_ * AST + c4_ * 4) * 2; \
            *reinterpret_cast<uint2*>(sAh_ + off) = make_uint2(p0, p1); \
        } \
    } while (0)

#define G1_CPB(c, stg) do { \
        const int kk_ = (c) * 64; \
        char* sB_ = dyn + (stg) * G1_STAGE + G1_AB; \
        uint32_t bU = smem_u32(sB_); \
        _Pragma("unroll") \
        for (int it = 0; it < 8; it++) { \
            int idx = tid + it * 256; \
            int n_ = idx >> 3, c8_ = idx & 7; \
            int off = (n_ * AST + c8_ * 8) * 2; \
            cpasync16(bU + off, g_w1 + (size_t)n_ * DK + kk_ + c8_ * 8); \
        } \
        cpasync_commit(); \
    } while (0)

    G1_CPB(0, 0);
    G1_LDA(0);
    G1_STA(0);
    cpasync_wait0();
    __syncthreads();

    // B paired-x4 base: row = wn*32 + (lane&7) + ((lane>>4)&1)*8 ; koff = ((lane>>3)&1)*8
    const uint32_t bOff4 = (((wn * 32 + (lane & 7) + lhalf * 8) * AST)
                            + (((lane >> 3) & 1) * 8)) * 2;
    const uint32_t aOff  = (ln16 * AST + lhalf * 8) * 2;

    const int NC = DK / 64;   // 8
    for (int c = 0; c < NC; c++) {
        const int s = c & 1;
        if (c + 1 < NC) {
            G1_CPB(c + 1, s ^ 1);
            G1_LDA(c + 1);
        }

        {
            char* st = dyn + s * G1_STAGE;
            uint32_t sAhU = smem_u32(st);
            uint32_t sBU  = sAhU + G1_AB;

#pragma unroll
            for (int ks = 0; ks < 4; ks++) {
                const uint32_t ko = ks * 32;
                uint32_t Ah[4][4], B01[4], B23[4];
#pragma unroll
                for (int t = 0; t < 4; t++)
                    ldmatrix_x4(Ah[t], sAhU + aOff + (t * 16 * AST) * 2 + ko);
                ldmatrix_x4(B01, sBU + bOff4 + ko);
                ldmatrix_x4(B23, sBU + bOff4 + (16 * AST) * 2 + ko);
#pragma unroll
                for (int t = 0; t < 4; t++) {
                    mma_f16(acc[t][0][0], acc[t][0][1], acc[t][0][2], acc[t][0][3],
                            Ah[t][0], Ah[t][1], Ah[t][2], Ah[t][3], B01[0], B01[1]);
                    mma_f16(acc[t][1][0], acc[t][1][1], acc[t][1][2], acc[t][1][3],
                            Ah[t][0], Ah[t][1], Ah[t][2], Ah[t][3], B01[2], B01[3]);
                    mma_f16(acc[t][2][0], acc[t][2][1], acc[t][2][2], acc[t][2][3],
                            Ah[t][0], Ah[t][1], Ah[t][2], Ah[t][3], B23[0], B23[1]);
                    mma_f16(acc[t][3][0], acc[t][3][1], acc[t][3][2], acc[t][3][3],
                            Ah[t][0], Ah[t][1], Ah[t][2], Ah[t][3], B23[2], B23[3]);
                }
            }
        }

        if (c + 1 < NC) {
            G1_STA(s ^ 1);
            cpasync_wait0();
            __syncthreads();
        }
    }

    // ---- epilogue: bias, store hraw (fp16), column partial stats ----
    float css0[4], css1[4], cqq0[4], cqq1[4];
#pragma unroll
    for (int u = 0; u < 4; u++) {
        const int col = wn * 32 + u * 8 + tg * 2;
        const float bi0 = b1[col], bi1 = b1[col + 1];
        float cs0 = 0.f, cs1 = 0.f, cq0 = 0.f, cq1 = 0.f;
#pragma unroll
        for (int t = 0; t < 4; t++) {
            const int r = row0 + t * 16 + g;
            float v0 = acc[t][u][0] + bi0;
            float v1 = acc[t][u][1] + bi1;
            float v2 = acc[t][u][2] + bi0;
            float v3 = acc[t][u][3] + bi1;
            *reinterpret_cast<uint32_t*>(
                &g_hraw[((size_t)z * NROWS + r) * HH + col])     = pack_h2(v0, v1);
            *reinterpret_cast<uint32_t*>(
                &g_hraw[((size_t)z * NROWS + r + 8) * HH + col]) = pack_h2(v2, v3);
            cs0 += v0 + v2; cs1 += v1 + v3;
            cq0 += v0 * v0 + v2 * v2; cq1 += v1 * v1 + v3 * v3;
        }
        css0[u] = cs0; css1[u] = cs1; cqq0[u] = cq0; cqq1[u] = cq1;
    }
#pragma unroll
    for (int off = 4; off < 32; off <<= 1) {
#pragma unroll
        for (int u = 0; u < 4; u++) {
            css0[u] += __shfl_xor_sync(0xffffffffu, css0[u], off);
            css1[u] += __shfl_xor_sync(0xffffffffu, css1[u], off);
            cqq0[u] += __shfl_xor_sync(0xffffffffu, cqq0[u], off);
            cqq1[u] += __shfl_xor_sync(0xffffffffu, cqq1[u], off);
        }
    }
    if (g == 0) {
#pragma unroll
        for (int u = 0; u < 4; u++) {
            const int col = wn * 32 + u * 8 + tg * 2;
            const size_t base = ((size_t)z * NRB1 + rb) * HH + col;
            g_psum[base]     = css0[u];
            g_psum[base + 1] = css1[u];
            g_psq [base]     = cqq0[u];
            g_psq [base + 1] = cqq1[u];
        }
    }
#undef G1_LDA
#undef G1_STA
#undef G1_CPB
}

// ---------------------------------------------------------------------------
// Stats: one block per (z, column); 256 threads reduce NRB1 partials.
// ---------------------------------------------------------------------------
__global__ void __launch_bounds__(256) stats_kernel(
    const float* __restrict__ gamma, const float* __restrict__ beta_bn)
{
    const int z = blockIdx.x >> 8;
    const int c = blockIdx.x & 255;
    const int tid = threadIdx.x;

    float s = 0.0f, q = 0.0f;
    for (int i = tid; i < NRB1; i += 256) {
        s += g_psum[((size_t)z * NRB1 + i) * HH + c];
        q += g_psq [((size_t)z * NRB1 + i) * HH + c];
    }
#pragma unroll
    for (int off = 16; off > 0; off >>= 1) {
        s += __shfl_xor_sync(0xffffffffu, s, off);
        q += __shfl_xor_sync(0xffffffffu, q, off);
    }
    __shared__ float rs[8], rq[8];
    if ((tid & 31) == 0) { rs[tid >> 5] = s; rq[tid >> 5] = q; }
    __syncthreads();
    if (tid == 0) {
        float S = 0.f, Q = 0.f;
#pragma unroll
        for (int w = 0; w < 8; w++) { S += rs[w]; Q += rq[w]; }
        const float mean = S / (float)NROWS;
        const float var  = Q / (float)NROWS - mean * mean;
        const float sc   = gamma[c] * rsqrtf(var + 1e-5f);
        g_scale[z * HH + c] = sc;
        g_shift[z * HH + c] = beta_bn[c] - mean * sc;
    }
}

// ---------------------------------------------------------------------------
// FUSED v5: 64-row CTAs, 2 CTAs/SM; B fragments loaded pairwise via x4.
// 8 warps (2m x 4n): GEMM2 warp tile 32x32, GEMM3 warp tile 32x16.
// ---------------------------------------------------------------------------
#define F2_AB   (64 * AST * 2)         // 9216 (single A stage)
#define F2_AREG (2 * F2_AB)            // 18432
#define F2_BB   (128 * AST * 2)        // 18432
#define F2_BREG (2 * F2_BB)            // 36864
#define F2_DYN  (F2_AREG + F2_BREG)    // 55296
#define ST3 136

__global__ void __launch_bounds__(256, 2) fused2(
    const float* __restrict__ b2, const float* __restrict__ b3,
    const float* __restrict__ W4, const float* __restrict__ b4,
    const float* __restrict__ alphap, const float* __restrict__ betap,
    float* __restrict__ out)
{
    extern __shared__ char dyn[];
    __shared__ float s_sc[HH];
    __shared__ float s_sh[HH];
    __shared__ float s_red[4][64][4];

    const int rb   = blockIdx.x;
    const int row0 = rb * 64;
    const int tid  = threadIdx.x;
    const int lane = tid & 31;
    const int wid  = tid >> 5;
    const int wm   = wid >> 2;       // 0..1
    const int wn   = wid & 3;        // 0..3
    const int g    = lane >> 2;
    const int tg   = lane & 3;
    const int ln16 = lane & 15;
    const int lhalf = (lane >> 4) & 1;

    char* Areg = dyn;
    char* Breg = dyn + F2_AREG;

    float acc[2][4][4];
    float h1[2][4][4];
    uint4 aNext[2];

    const uint32_t aOff2 = ((wm * 32 + ln16) * AST + lhalf * 8) * 2;
    // paired B x4: row = wn*32 + (lane&7) + lhalf*8 ; koff = ((lane>>3)&1)*8
    const uint32_t bOff4 = (((wn * 32 + (lane & 7) + lhalf * 8) * AST)
                            + (((lane >> 3) & 1) * 8)) * 2;

#define F2_LDA(zz, c) do { \
        const int kk_ = (c) * 64; \
        _Pragma("unroll") \
        for (int it = 0; it < 2; it++) { \
            int idx = tid + it * 256; \
            int r_  = idx >> 3, c8_ = idx & 7; \
            aNext[it] = *reinterpret_cast<const uint4*>( \
                g_hraw + ((size_t)(zz) * NROWS + row0 + r_) * HH + kk_ + c8_ * 8); \
        } \
    } while (0)

#define F2_STA(c, stg) do { \
        const int kk_ = (c) * 64; \
        char* sA_ = Areg + (stg) * F2_AB; \
        _Pragma("unroll") \
        for (int it = 0; it < 2; it++) { \
            int idx = tid + it * 256; \
            int r_  = idx >> 3, c8_ = idx & 7; \
            const int col_ = kk_ + c8_ * 8; \
            float2 f0 = unpack_h2(aNext[it].x); \
            float2 f1 = unpack_h2(aNext[it].y); \
            float2 f2 = unpack_h2(aNext[it].z); \
            float2 f3 = unpack_h2(aNext[it].w); \
            float a0 = fmaxf(s_sc[col_ + 0] * f0.x + s_sh[col_ + 0], 0.0f); \
            float a1 = fmaxf(s_sc[col_ + 1] * f0.y + s_sh[col_ + 1], 0.0f); \
            float a2 = fmaxf(s_sc[col_ + 2] * f1.x + s_sh[col_ + 2], 0.0f); \
            float a3 = fmaxf(s_sc[col_ + 3] * f1.y + s_sh[col_ + 3], 0.0f); \
            float a4 = fmaxf(s_sc[col_ + 4] * f2.x + s_sh[col_ + 4], 0.0f); \
            float a5 = fmaxf(s_sc[col_ + 5] * f2.y + s_sh[col_ + 5], 0.0f); \
            float a6 = fmaxf(s_sc[col_ + 6] * f3.x + s_sh[col_ + 6], 0.0f); \
            float a7 = fmaxf(s_sc[col_ + 7] * f3.y + s_sh[col_ + 7], 0.0f); \
            int off = (r_ * AST + c8_ * 8) * 2; \
            *reinterpret_cast<uint4*>(sA_ + off) = \
                make_uint4(pack_h2(a0, a1), pack_h2(a2, a3), \
                           pack_h2(a4, a5), pack_h2(a6, a7)); \
        } \
    } while (0)

#define F2_CPB(c, stg) do { \
        const int kk_ = (c) * 64; \
        char* sB_ = Breg + (stg) * F2_BB; \
        uint32_t bU = smem_u32(sB_); \
        _Pragma("unroll") \
        for (int it = 0; it < 4; it++) { \
            int idx = tid + it * 256; \
            int n_ = idx >> 3, c8_ = idx & 7; \
            int off = (n_ * AST + c8_ * 8) * 2; \
            cpasync16(bU + off, g_w2 + (size_t)n_ * HH + kk_ + c8_ * 8); \
        } \
        cpasync_commit(); \
    } while (0)

    // ========================= Phases 1 & 2: GEMM2 x2 =======================
    for (int z = 0; z < 2; z++) {
        __syncthreads();
        s_sc[tid] = g_scale[z * HH + tid];
        s_sh[tid] = g_shift[z * HH + tid];
        __syncthreads();

#pragma unroll
        for (int t = 0; t < 2; t++)
#pragma unroll
            for (int u = 0; u < 4; u++)
#pragma unroll
                for (int j = 0; j < 4; j++) acc[t][u][j] = 0.0f;

        F2_CPB(0, 0);
        F2_LDA(z, 0);
        F2_STA(0, 0);
        cpasync_wait0();
        __syncthreads();

        const int NC = 4;
        for (int c = 0; c < NC; c++) {
            const int s = c & 1;
            if (c + 1 < NC) {
                F2_CPB(c + 1, s ^ 1);
                F2_LDA(z, c + 1);
            }
            {
                uint32_t sAU = smem_u32(Areg + s * F2_AB);
                uint32_t sBU = smem_u32(Breg + s * F2_BB);
#pragma unroll
                for (int ks = 0; ks < 4; ks++) {
                    const uint32_t ko = ks * 32;
                    uint32_t Ah[2][4], B01[4], B23[4];
#pragma unroll
                    for (int t = 0; t < 2; t++)
                        ldmatrix_x4(Ah[t], sAU + aOff2 + (t * 16 * AST) * 2 + ko);
                    ldmatrix_x4(B01, sBU + bOff4 + ko);
                    ldmatrix_x4(B23, sBU + bOff4 + (16 * AST) * 2 + ko);
#pragma unroll
                    for (int t = 0; t < 2; t++) {
                        mma_f16(acc[t][0][0], acc[t][0][1], acc[t][0][2], acc[t][0][3],
                                Ah[t][0], Ah[t][1], Ah[t][2], Ah[t][3], B01[0], B01[1]);
                        mma_f16(acc[t][1][0], acc[t][1][1], acc[t][1][2], acc[t][1][3],
                                Ah[t][0], Ah[t][1], Ah[t][2], Ah[t][3], B01[2], B01[3]);
                        mma_f16(acc[t][2][0], acc[t][2][1], acc[t][2][2], acc[t][2][3],
                                Ah[t][0], Ah[t][1], Ah[t][2], Ah[t][3], B23[0], B23[1]);
                        mma_f16(acc[t][3][0], acc[t][3][1], acc[t][3][2], acc[t][3][3],
                                Ah[t][0], Ah[t][1], Ah[t][2], Ah[t][3], B23[2], B23[3]);
                    }
                }
            }
            if (c + 1 < NC) {
                __syncthreads();
                F2_STA(c + 1, s ^ 1);
                cpasync_wait0();
                __syncthreads();
            }
        }

        // epilogue: h = relu(acc + b2); stash into h1 (z=0) or keep in acc (z=1)
#pragma unroll
        for (int u = 0; u < 4; u++) {
            const int col = wn * 32 + u * 8 + tg * 2;
            const float bi0 = b2[col], bi1 = b2[col + 1];
#pragma unroll
            for (int t = 0; t < 2; t++) {
                float v0 = fmaxf(acc[t][u][0] + bi0, 0.0f);
                float v1 = fmaxf(acc[t][u][1] + bi1, 0.0f);
                float v2 = fmaxf(acc[t][u][2] + bi0, 0.0f);
                float v3 = fmaxf(acc[t][u][3] + bi1, 0.0f);
                if (z == 0) {
                    h1[t][u][0] = v0; h1[t][u][1] = v1;
                    h1[t][u][2] = v2; h1[t][u][3] = v3;
                } else {
                    acc[t][u][0] = v0; acc[t][u][1] = v1;
                    acc[t][u][2] = v2; acc[t][u][3] = v3;
                }
            }
        }
    }

    // ================== cosine partials (row-wise) from fragments ==========
    {
        float dotR[4], n1R[4], n2R[4];
#pragma unroll
        for (int ri = 0; ri < 4; ri++) { dotR[ri] = 0.f; n1R[ri] = 0.f; n2R[ri] = 0.f; }
#pragma unroll
        for (int t = 0; t < 2; t++)
#pragma unroll
            for (int u = 0; u < 4; u++)
#pragma unroll
                for (int j = 0; j < 4; j++) {
                    const float a = h1[t][u][j];
                    const float b = acc[t][u][j];
                    const int ri = t * 2 + (j >> 1);
                    dotR[ri] = fmaf(a, b, dotR[ri]);
                    n1R[ri]  = fmaf(a, a, n1R[ri]);
                    n2R[ri]  = fmaf(b, b, n2R[ri]);
                }
#pragma unroll
        for (int off = 1; off < 4; off <<= 1) {
#pragma unroll
            for (int ri = 0; ri < 4; ri++) {
                dotR[ri] += __shfl_xor_sync(0xffffffffu, dotR[ri], off);
                n1R[ri]  += __shfl_xor_sync(0xffffffffu, n1R[ri], off);
                n2R[ri]  += __shfl_xor_sync(0xffffffffu, n2R[ri], off);
            }
        }
        if (tg == 0) {
#pragma unroll
            for (int ri = 0; ri < 4; ri++) {
                const int r = wm * 32 + (ri >> 1) * 16 + g + (ri & 1) * 8;
                s_red[0][r][wn] = dotR[ri];
                s_red[1][r][wn] = n1R[ri];
                s_red[2][r][wn] = n2R[ri];
            }
        }
    }

    // ==================== Phase 3: GEMM3 on tensor cores (1-pass) ===========
    float acc3[2][2][4];
#pragma unroll
    for (int t = 0; t < 2; t++)
#pragma unroll
        for (int u = 0; u < 2; u++)
#pragma unroll
            for (int j = 0; j < 4; j++) acc3[t][u][j] = 0.0f;

    const uint32_t aOff3 = ((wm * 32 + ln16) * ST3 + lhalf * 8) * 2;
    // paired B x4 for GEMM3: both u fragments (16 rows) in one x4
    const uint32_t bOff3_4 = (((wn * 16 + (lane & 7) + lhalf * 8) * ST3)
                              + (((lane >> 3) & 1) * 8)) * 2;
    char* A3 = Areg;                         // 64*136*2 = 17408 <= 18432
    uint32_t A3U = smem_u32(A3);
    uint32_t B3U = smem_u32(Breg);           // 64*136*2 = 17408 <= 36864

    __syncthreads();   // all warps done with phase-2 stages + s_red written

    for (int f = 0; f < 3; f++) {
        // prefetch W3 chunk f (64 x 128 halves)
#pragma unroll
        for (int it = 0; it < 4; it++) {
            int idx = tid + it * 256;
            int n_ = idx >> 4, cc = idx & 15;
            int off = (n_ * ST3 + cc * 8) * 2;
            cpasync16(B3U + off, g_w3 + n_ * 384 + f * 128 + cc * 8);
        }
        cpasync_commit();

        // write combined feature tile into A region (single fp16, stride ST3)
#pragma unroll
        for (int t = 0; t < 2; t++)
#pragma unroll
            for (int u = 0; u < 4; u++) {
                const int col = wn * 32 + u * 8 + tg * 2;
                const int r   = wm * 32 + t * 16 + g;
                float v[4];
#pragma unroll
                for (int j = 0; j < 4; j++) {
                    const float a = h1[t][u][j];
                    const float b = acc[t][u][j];
                    v[j] = (f == 0) ? a * b : (f == 1) ? fabsf(a - b) : a + b;
                }
                *reinterpret_cast<uint32_t*>(A3 + (r * ST3 + col) * 2)       = pack_h2(v[0], v[1]);
                *reinterpret_cast<uint32_t*>(A3 + ((r + 8) * ST3 + col) * 2) = pack_h2(v[2], v[3]);
            }
        cpasync_wait0();
        __syncthreads();

        // MMA over k=128 (8 steps), single pass; one B x4 covers both u's
#pragma unroll
        for (int ks = 0; ks < 8; ks++) {
            const uint32_t ko = ks * 32;
            uint32_t Ah[2][4], B01[4];
#pragma unroll
            for (int t = 0; t < 2; t++)
                ldmatrix_x4(Ah[t], A3U + aOff3 + (t * 16 * ST3) * 2 + ko);
            ldmatrix_x4(B01, B3U + bOff3_4 + ko);
#pragma unroll
            for (int t = 0; t < 2; t++) {
                mma_f16(acc3[t][0][0], acc3[t][0][1], acc3[t][0][2], acc3[t][0][3],
                        Ah[t][0], Ah[t][1], Ah[t][2], Ah[t][3], B01[0], B01[1]);
                mma_f16(acc3[t][1][0], acc3[t][1][1], acc3[t][1][2], acc3[t][1][3],
                        Ah[t][0], Ah[t][1], Ah[t][2], Ah[t][3], B01[2], B01[3]);
            }
        }
        __syncthreads();
    }

    // ==================== Phase 4: relu -> W4 -> head =======================
    {
        float slR[4];
#pragma unroll
        for (int ri = 0; ri < 4; ri++) slR[ri] = 0.0f;
#pragma unroll
        for (int u = 0; u < 2; u++) {
            const int col = wn * 16 + u * 8 + tg * 2;
            const float b30 = b3[col], b31 = b3[col + 1];
            const float w40 = W4[col], w41 = W4[col + 1];
#pragma unroll
            for (int t = 0; t < 2; t++) {
                slR[t * 2 + 0] += fmaxf(acc3[t][u][0] + b30, 0.0f) * w40
                                + fmaxf(acc3[t][u][1] + b31, 0.0f) * w41;
                slR[t * 2 + 1] += fmaxf(acc3[t][u][2] + b30, 0.0f) * w40
                                + fmaxf(acc3[t][u][3] + b31, 0.0f) * w41;
            }
        }
#pragma unroll
        for (int off = 1; off < 4; off <<= 1)
#pragma unroll
            for (int ri = 0; ri < 4; ri++)
                slR[ri] += __shfl_xor_sync(0xffffffffu, slR[ri], off);
        if (tg == 0) {
#pragma unroll
            for (int ri = 0; ri < 4; ri++) {
                const int r = wm * 32 + (ri >> 1) * 16 + g + (ri & 1) * 8;
                s_red[3][r][wn] = slR[ri];
            }
        }
    }
    __syncthreads();

    if (tid < 64) {
        float dot = 0.f, n1v = 0.f, n2v = 0.f, sl = 0.f;
#pragma unroll
        for (int w = 0; w < 4; w++) {
            dot += s_red[0][tid][w];
            n1v += s_red[1][tid][w];
            n2v += s_red[2][tid][w];
            sl  += s_red[3][tid][w];
        }
        const float inv1   = 1.0f / fmaxf(sqrtf(n1v), 1e-15f);
        const float inv2   = 1.0f / fmaxf(sqrtf(n2v), 1e-15f);
        const float s_math = fminf(fmaxf(dot * inv1 * inv2, 0.0f), 1.0f);
        const float sig    = 1.0f / (1.0f + expf(-(sl + b4[0])));
        const float fin    = alphap[0] * s_math + betap[0] * sig;
        out[row0 + tid] = fminf(fmaxf(fin, 0.0f), 1.0f);
    }
#undef F2_LDA
#undef F2_STA
#undef F2_CPB
}

// ---------------------------------------------------------------------------
extern "C" void kernel_launch(void* const* d_in, const int* in_sizes, int n_in,
                              void* d_out, int out_size)
{
    const float* x1      = (const float*)d_in[0];
    const float* x2      = (const float*)d_in[1];
    const float* W1      = (const float*)d_in[2];
    const float* b1      = (const float*)d_in[3];
    const float* gamma   = (const float*)d_in[4];
    const float* beta_bn = (const float*)d_in[5];
    const float* W2      = (const float*)d_in[6];
    const float* b2      = (const float*)d_in[7];
    const float* W3      = (const float*)d_in[8];
    const float* b3      = (const float*)d_in[9];
    const float* W4      = (const float*)d_in[10];
    const float* b4      = (const float*)d_in[11];
    const float* alphap  = (const float*)d_in[12];
    const float* betap   = (const float*)d_in[13];
    float* out = (float*)d_out;

    cudaFuncSetAttribute(gemm1_mma,
                         cudaFuncAttributeMaxDynamicSharedMemorySize, G1_DYN);
    cudaFuncSetAttribute(fused2,
                         cudaFuncAttributeMaxDynamicSharedMemorySize, F2_DYN);

    const int prep_elems = DK * HH + HH * H2 + 384 * O3;
    prep_weights<<<(prep_elems + 255) / 256, 256>>>(W1, W2, W3);

    dim3 g1(NRB1, 2);
    gemm1_mma<<<g1, 256, G1_DYN>>>(x1, x2, b1);

    stats_kernel<<<512, 256>>>(gamma, beta_bn);

    fused2<<<NRB2, 256, F2_DYN>>>(b2, b3, W4, b4, alphap, betap, out);
}

// round 15
// speedup vs baseline: 1.0898x; 1.0588x over previous
#include <cuda_runtime.h>
#include <cuda_bf16.h>
#include <cuda_fp16.h>
#include <cstdint>
#include <math.h>

// ---------------------------------------------------------------------------
// Problem constants
// ---------------------------------------------------------------------------
#define NROWS 65536
#define DK    512
#define HH    256
#define H2    128
#define O3    64
#define NRB1  1024          // gemm1 row blocks of 64
#define NRB2  1024          // fused2 row blocks of 64

// ---------------------------------------------------------------------------
// Scratch (device globals — allocation-free per harness rules)
// ---------------------------------------------------------------------------
__device__ __align__(16) __half g_hraw[2 * NROWS * HH];   // 64 MB fp16 pre-BN
__device__ float g_psum[2 * NRB1 * HH];
__device__ float g_psq [2 * NRB1 * HH];
__device__ float g_scale[2 * HH];
__device__ float g_shift[2 * HH];
// All weights single fp16, transposed K-major [N][K]
__device__ __align__(16) __half g_w1[HH * DK];
__device__ __align__(16) __half g_w2[H2 * HH];
__device__ __align__(16) __half g_w3[O3 * 384];

// ---------------------------------------------------------------------------
// Warp-MMA helpers (base PTX — no sm_103a-only features)
// ---------------------------------------------------------------------------
__device__ __forceinline__ uint32_t smem_u32(const void* p) {
    uint32_t a;
    asm("{ .reg .u64 t; cvta.to.shared.u64 t, %1; cvt.u32.u64 %0, t; }"
        : "=r"(a) : "l"(p));
    return a;
}

__device__ __forceinline__ void mma_f16(float& c0, float& c1, float& c2, float& c3,
                                        uint32_t a0, uint32_t a1, uint32_t a2, uint32_t a3,
                                        uint32_t b0, uint32_t b1) {
    asm volatile(
        "mma.sync.aligned.m16n8k16.row.col.f32.f16.f16.f32 "
        "{%0,%1,%2,%3}, {%4,%5,%6,%7}, {%8,%9}, {%0,%1,%2,%3};"
        : "+f"(c0), "+f"(c1), "+f"(c2), "+f"(c3)
        : "r"(a0), "r"(a1), "r"(a2), "r"(a3), "r"(b0), "r"(b1));
}

__device__ __forceinline__ void ldmatrix_x4(uint32_t* r, uint32_t addr) {
    asm volatile("ldmatrix.sync.aligned.m8n8.x4.shared.b16 {%0,%1,%2,%3}, [%4];"
        : "=r"(r[0]), "=r"(r[1]), "=r"(r[2]), "=r"(r[3]) : "r"(addr));
}

__device__ __forceinline__ void cpasync16(uint32_t dst, const void* src) {
    asm volatile("cp.async.cg.shared.global [%0], [%1], 16;" :: "r"(dst), "l"(src));
}
__device__ __forceinline__ void cpasync_commit() {
    asm volatile("cp.async.commit_group;" ::: "memory");
}
__device__ __forceinline__ void cpasync_wait0() {
    asm volatile("cp.async.wait_group 0;" ::: "memory");
}

// pack (x,y) into one fp16x2 word
__device__ __forceinline__ uint32_t pack_h2(float x, float y) {
    __half2 h = __floats2half2_rn(x, y);
    return *reinterpret_cast<uint32_t*>(&h);
}

__device__ __forceinline__ float2 unpack_h2(uint32_t u) {
    __half2 h = *reinterpret_cast<__half2*>(&u);
    return __half22float2(h);
}

// ---------------------------------------------------------------------------
// Weight prep: transpose to K-major fp16. W1[256][512], W2[128][256], W3[64][384].
// ---------------------------------------------------------------------------
__global__ void prep_weights(const float* __restrict__ W1,
                             const float* __restrict__ W2,
                             const float* __restrict__ W3)
{
    int i = blockIdx.x * 256 + threadIdx.x;
    if (i < DK * HH) {
        int k = i >> 8, n = i & 255;
        g_w1[n * DK + k] = __float2half_rn(W1[i]);
        return;
    }
    int j = i - DK * HH;
    if (j < HH * H2) {
        int k = j >> 7, n = j & 127;
        g_w2[n * HH + k] = __float2half_rn(W2[j]);
        return;
    }
    int j2 = j - HH * H2;
    if (j2 < 384 * O3) {
        int k = j2 >> 6, n = j2 & 63;
        g_w3[n * 384 + k] = __float2half_rn(W3[j2]);
    }
}

// ---------------------------------------------------------------------------
// GEMM1 (unchanged from R14, passing): hraw(fp16) = X @ W1 + b1, plus stats.
// CTA 64x256, 256 threads, 8 warps (1m x 8n), warp tile 64x32, paired B-x4.
// ---------------------------------------------------------------------------
#define AST 72
#define G1_AB  (64 * AST * 2)                 // 9216
#define G1_BB  (256 * AST * 2)                // 36864
#define G1_STAGE (G1_AB + G1_BB)              // 46080
#define G1_DYN   (2 * G1_STAGE)               // 92160

__global__ void __launch_bounds__(256) gemm1_mma(
    const float* __restrict__ x1, const float* __restrict__ x2,
    const float* __restrict__ b1)
{
    extern __shared__ char dyn[];
    const int z    = blockIdx.y;
    const int rb   = blockIdx.x;
    const int row0 = rb * 64;
    const float* __restrict__ X = z ? x2 : x1;

    const int tid  = threadIdx.x;
    const int lane = tid & 31;
    const int wn   = tid >> 5;       // warp id = n-tile 0..7
    const int g    = lane >> 2;      // 0..7
    const int tg   = lane & 3;       // 0..3
    const int ln16 = lane & 15;
    const int lhalf = (lane >> 4) & 1;

    float acc[4][4][4];
#pragma unroll
    for (int t = 0; t < 4; t++)
#pragma unroll
        for (int u = 0; u < 4; u++)
#pragma unroll
            for (int j = 0; j < 4; j++) acc[t][u][j] = 0.0f;

    float4 aNext[4];

#define G1_LDA(c) do { \
        const int kk_ = (c) * 64; \
        _Pragma("unroll") \
        for (int it = 0; it < 4; it++) { \
            int idx = tid + it * 256; \
            int r_  = idx >> 4, c4_ = idx & 15; \
            aNext[it] = *reinterpret_cast<const float4*>( \
                X + (size_t)(row0 + r_) * DK + kk_ + c4_ * 4); \
        } \
    } while (0)

#define G1_STA(stg) do { \
        char* sAh_ = dyn + (stg) * G1_STAGE; \
        _Pragma("unroll") \
        for (int it = 0; it < 4; it++) { \
            int idx = tid + it * 256; \
            int r_  = idx >> 4, c4_ = idx & 15; \
            uint32_t p0 = pack_h2(aNext[it].x, aNext[it].y); \
            uint32_t p1 = pack_h2(aNext[it].z, aNext[it].w); \
            int off = (r_ * AST + c4_ * 4) * 2; \
            *reinterpret_cast<uint2*>(sAh_ + off) = make_uint2(p0, p1); \
        } \
    } while (0)

#define G1_CPB(c, stg) do { \
        const int kk_ = (c) * 64; \
        char* sB_ = dyn + (stg) * G1_STAGE + G1_AB; \
        uint32_t bU = smem_u32(sB_); \
        _Pragma("unroll") \
        for (int it = 0; it < 8; it++) { \
            int idx = tid + it * 256; \
            int n_ = idx >> 3, c8_ = idx & 7; \
            int off = (n_ * AST + c8_ * 8) * 2; \
            cpasync16(bU + off, g_w1 + (size_t)n_ * DK + kk_ + c8_ * 8); \
        } \
        cpasync_commit(); \
    } while (0)

    G1_CPB(0, 0);
    G1_LDA(0);
    G1_STA(0);
    cpasync_wait0();
    __syncthreads();

    const uint32_t bOff4 = (((wn * 32 + (lane & 7) + lhalf * 8) * AST)
                            + (((lane >> 3) & 1) * 8)) * 2;
    const uint32_t aOff  = (ln16 * AST + lhalf * 8) * 2;

    const int NC = DK / 64;   // 8
    for (int c = 0; c < NC; c++) {
        const int s = c & 1;
        if (c + 1 < NC) {
            G1_CPB(c + 1, s ^ 1);
            G1_LDA(c + 1);
        }

        {
            char* st = dyn + s * G1_STAGE;
            uint32_t sAhU = smem_u32(st);
            uint32_t sBU  = sAhU + G1_AB;

#pragma unroll
            for (int ks = 0; ks < 4; ks++) {
                const uint32_t ko = ks * 32;
                uint32_t Ah[4][4], B01[4], B23[4];
#pragma unroll
                for (int t = 0; t < 4; t++)
                    ldmatrix_x4(Ah[t], sAhU + aOff + (t * 16 * AST) * 2 + ko);
                ldmatrix_x4(B01, sBU + bOff4 + ko);
                ldmatrix_x4(B23, sBU + bOff4 + (16 * AST) * 2 + ko);
#pragma unroll
                for (int t = 0; t < 4; t++) {
                    mma_f16(acc[t][0][0], acc[t][0][1], acc[t][0][2], acc[t][0][3],
                            Ah[t][0], Ah[t][1], Ah[t][2], Ah[t][3], B01[0], B01[1]);
                    mma_f16(acc[t][1][0], acc[t][1][1], acc[t][1][2], acc[t][1][3],
                            Ah[t][0], Ah[t][1], Ah[t][2], Ah[t][3], B01[2], B01[3]);
                    mma_f16(acc[t][2][0], acc[t][2][1], acc[t][2][2], acc[t][2][3],
                            Ah[t][0], Ah[t][1], Ah[t][2], Ah[t][3], B23[0], B23[1]);
                    mma_f16(acc[t][3][0], acc[t][3][1], acc[t][3][2], acc[t][3][3],
                            Ah[t][0], Ah[t][1], Ah[t][2], Ah[t][3], B23[2], B23[3]);
                }
            }
        }

        if (c + 1 < NC) {
            G1_STA(s ^ 1);
            cpasync_wait0();
            __syncthreads();
        }
    }

    // ---- epilogue: bias, store hraw (fp16), column partial stats ----
    float css0[4], css1[4], cqq0[4], cqq1[4];
#pragma unroll
    for (int u = 0; u < 4; u++) {
        const int col = wn * 32 + u * 8 + tg * 2;
        const float bi0 = b1[col], bi1 = b1[col + 1];
        float cs0 = 0.f, cs1 = 0.f, cq0 = 0.f, cq1 = 0.f;
#pragma unroll
        for (int t = 0; t < 4; t++) {
            const int r = row0 + t * 16 + g;
            float v0 = acc[t][u][0] + bi0;
            float v1 = acc[t][u][1] + bi1;
            float v2 = acc[t][u][2] + bi0;
            float v3 = acc[t][u][3] + bi1;
            *reinterpret_cast<uint32_t*>(
                &g_hraw[((size_t)z * NROWS + r) * HH + col])     = pack_h2(v0, v1);
            *reinterpret_cast<uint32_t*>(
                &g_hraw[((size_t)z * NROWS + r + 8) * HH + col]) = pack_h2(v2, v3);
            cs0 += v0 + v2; cs1 += v1 + v3;
            cq0 += v0 * v0 + v2 * v2; cq1 += v1 * v1 + v3 * v3;
        }
        css0[u] = cs0; css1[u] = cs1; cqq0[u] = cq0; cqq1[u] = cq1;
    }
#pragma unroll
    for (int off = 4; off < 32; off <<= 1) {
#pragma unroll
        for (int u = 0; u < 4; u++) {
            css0[u] += __shfl_xor_sync(0xffffffffu, css0[u], off);
            css1[u] += __shfl_xor_sync(0xffffffffu, css1[u], off);
            cqq0[u] += __shfl_xor_sync(0xffffffffu, cqq0[u], off);
            cqq1[u] += __shfl_xor_sync(0xffffffffu, cqq1[u], off);
        }
    }
    if (g == 0) {
#pragma unroll
        for (int u = 0; u < 4; u++) {
            const int col = wn * 32 + u * 8 + tg * 2;
            const size_t base = ((size_t)z * NRB1 + rb) * HH + col;
            g_psum[base]     = css0[u];
            g_psum[base + 1] = css1[u];
            g_psq [base]     = cqq0[u];
            g_psq [base + 1] = cqq1[u];
        }
    }
#undef G1_LDA
#undef G1_STA
#undef G1_CPB
}

// ---------------------------------------------------------------------------
// Stats: one block per (z, column); 256 threads reduce NRB1 partials.
// ---------------------------------------------------------------------------
__global__ void __launch_bounds__(256) stats_kernel(
    const float* __restrict__ gamma, const float* __restrict__ beta_bn)
{
    const int z = blockIdx.x >> 8;
    const int c = blockIdx.x & 255;
    const int tid = threadIdx.x;

    float s = 0.0f, q = 0.0f;
    for (int i = tid; i < NRB1; i += 256) {
        s += g_psum[((size_t)z * NRB1 + i) * HH + c];
        q += g_psq [((size_t)z * NRB1 + i) * HH + c];
    }
#pragma unroll
    for (int off = 16; off > 0; off >>= 1) {
        s += __shfl_xor_sync(0xffffffffu, s, off);
        q += __shfl_xor_sync(0xffffffffu, q, off);
    }
    __shared__ float rs[8], rq[8];
    if ((tid & 31) == 0) { rs[tid >> 5] = s; rq[tid >> 5] = q; }
    __syncthreads();
    if (tid == 0) {
        float S = 0.f, Q = 0.f;
#pragma unroll
        for (int w = 0; w < 8; w++) { S += rs[w]; Q += rq[w]; }
        const float mean = S / (float)NROWS;
        const float var  = Q / (float)NROWS - mean * mean;
        const float sc   = gamma[c] * rsqrtf(var + 1e-5f);
        g_scale[z * HH + c] = sc;
        g_shift[z * HH + c] = beta_bn[c] - mean * sc;
    }
}

// ---------------------------------------------------------------------------
// FUSED v6: merged z-loop. For each k-chunk, stage A tiles for BOTH inputs
// and load B once; accumulate h1 (z0) and acc (z1) in the same mainloop.
// Halves B cp.async + B LDSM and halves sync/pipeline overhead.
// 64-row CTAs, 2 CTAs/SM. 8 warps (2m x 4n), GEMM2 tile 32x32, GEMM3 32x16.
// smem: A 2 stages x 2 z x 9216 = 36864 | B 2 stages x 18432 = 36864.
// ---------------------------------------------------------------------------
#define F2_AB   (64 * AST * 2)         // 9216 per (stage, z)
#define F2_ASTG (2 * F2_AB)            // 18432 per stage (both z)
#define F2_AREG (2 * F2_ASTG)          // 36864
#define F2_BB   (128 * AST * 2)        // 18432
#define F2_BREG (2 * F2_BB)            // 36864
#define F2_DYN  (F2_AREG + F2_BREG)    // 73728
#define ST3 136

__global__ void __launch_bounds__(256, 2) fused2(
    const float* __restrict__ b2, const float* __restrict__ b3,
    const float* __restrict__ W4, const float* __restrict__ b4,
    const float* __restrict__ alphap, const float* __restrict__ betap,
    float* __restrict__ out)
{
    extern __shared__ char dyn[];
    __shared__ float s_sc[2][HH];
    __shared__ float s_sh[2][HH];
    __shared__ float s_red[4][64][4];

    const int rb   = blockIdx.x;
    const int row0 = rb * 64;
    const int tid  = threadIdx.x;
    const int lane = tid & 31;
    const int wid  = tid >> 5;
    const int wm   = wid >> 2;       // 0..1
    const int wn   = wid & 3;        // 0..3
    const int g    = lane >> 2;
    const int tg   = lane & 3;
    const int ln16 = lane & 15;
    const int lhalf = (lane >> 4) & 1;

    char* Areg = dyn;
    char* Breg = dyn + F2_AREG;

    float h1[2][4][4];    // z0 accumulators
    float acc[2][4][4];   // z1 accumulators
    uint4 aN0[2], aN1[2];

    const uint32_t aOff2 = ((wm * 32 + ln16) * AST + lhalf * 8) * 2;
    const uint32_t bOff4 = (((wn * 32 + (lane & 7) + lhalf * 8) * AST)
                            + (((lane >> 3) & 1) * 8)) * 2;

#define F2_LDA(zz, c, arr) do { \
        const int kk_ = (c) * 64; \
        _Pragma("unroll") \
        for (int it = 0; it < 2; it++) { \
            int idx = tid + it * 256; \
            int r_  = idx >> 3, c8_ = idx & 7; \
            arr[it] = *reinterpret_cast<const uint4*>( \
                g_hraw + ((size_t)(zz) * NROWS + row0 + r_) * HH + kk_ + c8_ * 8); \
        } \
    } while (0)

#define F2_STA(c, stg, zz, arr) do { \
        const int kk_ = (c) * 64; \
        char* sA_ = Areg + (stg) * F2_ASTG + (zz) * F2_AB; \
        _Pragma("unroll") \
        for (int it = 0; it < 2; it++) { \
            int idx = tid + it * 256; \
            int r_  = idx >> 3, c8_ = idx & 7; \
            const int col_ = kk_ + c8_ * 8; \
            float2 f0 = unpack_h2(arr[it].x); \
            float2 f1 = unpack_h2(arr[it].y); \
            float2 f2 = unpack_h2(arr[it].z); \
            float2 f3 = unpack_h2(arr[it].w); \
            float a0 = fmaxf(s_sc[zz][col_ + 0] * f0.x + s_sh[zz][col_ + 0], 0.0f); \
            float a1 = fmaxf(s_sc[zz][col_ + 1] * f0.y + s_sh[zz][col_ + 1], 0.0f); \
            float a2 = fmaxf(s_sc[zz][col_ + 2] * f1.x + s_sh[zz][col_ + 2], 0.0f); \
            float a3 = fmaxf(s_sc[zz][col_ + 3] * f1.y + s_sh[zz][col_ + 3], 0.0f); \
            float a4 = fmaxf(s_sc[zz][col_ + 4] * f2.x + s_sh[zz][col_ + 4], 0.0f); \
            float a5 = fmaxf(s_sc[zz][col_ + 5] * f2.y + s_sh[zz][col_ + 5], 0.0f); \
            float a6 = fmaxf(s_sc[zz][col_ + 6] * f3.x + s_sh[zz][col_ + 6], 0.0f); \
            float a7 = fmaxf(s_sc[zz][col_ + 7] * f3.y + s_sh[zz][col_ + 7], 0.0f); \
            int off = (r_ * AST + c8_ * 8) * 2; \
            *reinterpret_cast<uint4*>(sA_ + off) = \
                make_uint4(pack_h2(a0, a1), pack_h2(a2, a3), \
                           pack_h2(a4, a5), pack_h2(a6, a7)); \
        } \
    } while (0)

#define F2_CPB(c, stg) do { \
        const int kk_ = (c) * 64; \
        char* sB_ = Breg + (stg) * F2_BB; \
        uint32_t bU = smem_u32(sB_); \
        _Pragma("unroll") \
        for (int it = 0; it < 4; it++) { \
            int idx = tid + it * 256; \
            int n_ = idx >> 3, c8_ = idx & 7; \
            int off = (n_ * AST + c8_ * 8) * 2; \
            cpasync16(bU + off, g_w2 + (size_t)n_ * HH + kk_ + c8_ * 8); \
        } \
        cpasync_commit(); \
    } while (0)

    // ================== Phase 1: GEMM2 for both z, single k-loop ============
    s_sc[0][tid & 255] = g_scale[tid];          // tid 0..255 covers z0
    s_sh[0][tid & 255] = g_shift[tid];
    s_sc[1][tid & 255] = g_scale[HH + tid];
    s_sh[1][tid & 255] = g_shift[HH + tid];

#pragma unroll
    for (int t = 0; t < 2; t++)
#pragma unroll
        for (int u = 0; u < 4; u++)
#pragma unroll
            for (int j = 0; j < 4; j++) { h1[t][u][j] = 0.0f; acc[t][u][j] = 0.0f; }

    F2_CPB(0, 0);
    F2_LDA(0, 0, aN0);
    F2_LDA(1, 0, aN1);
    __syncthreads();          // s_sc/s_sh visible before STA
    F2_STA(0, 0, 0, aN0);
    F2_STA(0, 0, 1, aN1);
    cpasync_wait0();
    __syncthreads();

    {
        const int NC = 4;
        for (int c = 0; c < NC; c++) {
            const int s = c & 1;
            if (c + 1 < NC) {
                F2_CPB(c + 1, s ^ 1);
                F2_LDA(0, c + 1, aN0);
                F2_LDA(1, c + 1, aN1);
            }
            {
                uint32_t A0U = smem_u32(Areg + s * F2_ASTG);
                uint32_t A1U = A0U + F2_AB;
                uint32_t sBU = smem_u32(Breg + s * F2_BB);
#pragma unroll
                for (int ks = 0; ks < 4; ks++) {
                    const uint32_t ko = ks * 32;
                    uint32_t A0[2][4], A1[2][4], B01[4], B23[4];
#pragma unroll
                    for (int t = 0; t < 2; t++)
                        ldmatrix_x4(A0[t], A0U + aOff2 + (t * 16 * AST) * 2 + ko);
#pragma unroll
                    for (int t = 0; t < 2; t++)
                        ldmatrix_x4(A1[t], A1U + aOff2 + (t * 16 * AST) * 2 + ko);
                    ldmatrix_x4(B01, sBU + bOff4 + ko);
                    ldmatrix_x4(B23, sBU + bOff4 + (16 * AST) * 2 + ko);
#pragma unroll
                    for (int t = 0; t < 2; t++) {
                        mma_f16(h1[t][0][0], h1[t][0][1], h1[t][0][2], h1[t][0][3],
                                A0[t][0], A0[t][1], A0[t][2], A0[t][3], B01[0], B01[1]);
                        mma_f16(h1[t][1][0], h1[t][1][1], h1[t][1][2], h1[t][1][3],
                                A0[t][0], A0[t][1], A0[t][2], A0[t][3], B01[2], B01[3]);
                        mma_f16(h1[t][2][0], h1[t][2][1], h1[t][2][2], h1[t][2][3],
                                A0[t][0], A0[t][1], A0[t][2], A0[t][3], B23[0], B23[1]);
                        mma_f16(h1[t][3][0], h1[t][3][1], h1[t][3][2], h1[t][3][3],
                                A0[t][0], A0[t][1], A0[t][2], A0[t][3], B23[2], B23[3]);
                        mma_f16(acc[t][0][0], acc[t][0][1], acc[t][0][2], acc[t][0][3],
                                A1[t][0], A1[t][1], A1[t][2], A1[t][3], B01[0], B01[1]);
                        mma_f16(acc[t][1][0], acc[t][1][1], acc[t][1][2], acc[t][1][3],
                                A1[t][0], A1[t][1], A1[t][2], A1[t][3], B01[2], B01[3]);
                        mma_f16(acc[t][2][0], acc[t][2][1], acc[t][2][2], acc[t][2][3],
                                A1[t][0], A1[t][1], A1[t][2], A1[t][3], B23[0], B23[1]);
                        mma_f16(acc[t][3][0], acc[t][3][1], acc[t][3][2], acc[t][3][3],
                                A1[t][0], A1[t][1], A1[t][2], A1[t][3], B23[2], B23[3]);
                    }
                }
            }
            if (c + 1 < NC) {
                __syncthreads();
                F2_STA(c + 1, s ^ 1, 0, aN0);
                F2_STA(c + 1, s ^ 1, 1, aN1);
                cpasync_wait0();
                __syncthreads();
            }
        }
    }

    // epilogue: bias + relu for both accumulator sets (in place)
#pragma unroll
    for (int u = 0; u < 4; u++) {
        const int col = wn * 32 + u * 8 + tg * 2;
        const float bi0 = b2[col], bi1 = b2[col + 1];
#pragma unroll
        for (int t = 0; t < 2; t++) {
            h1[t][u][0]  = fmaxf(h1[t][u][0]  + bi0, 0.0f);
            h1[t][u][1]  = fmaxf(h1[t][u][1]  + bi1, 0.0f);
            h1[t][u][2]  = fmaxf(h1[t][u][2]  + bi0, 0.0f);
            h1[t][u][3]  = fmaxf(h1[t][u][3]  + bi1, 0.0f);
            acc[t][u][0] = fmaxf(acc[t][u][0] + bi0, 0.0f);
            acc[t][u][1] = fmaxf(acc[t][u][1] + bi1, 0.0f);
            acc[t][u][2] = fmaxf(acc[t][u][2] + bi0, 0.0f);
            acc[t][u][3] = fmaxf(acc[t][u][3] + bi1, 0.0f);
        }
    }

    // ================== cosine partials (row-wise) from fragments ==========
    {
        float dotR[4], n1R[4], n2R[4];
#pragma unroll
        for (int ri = 0; ri < 4; ri++) { dotR[ri] = 0.f; n1R[ri] = 0.f; n2R[ri] = 0.f; }
#pragma unroll
        for (int t = 0; t < 2; t++)
#pragma unroll
            for (int u = 0; u < 4; u++)
#pragma unroll
                for (int j = 0; j < 4; j++) {
                    const float a = h1[t][u][j];
                    const float b = acc[t][u][j];
                    const int ri = t * 2 + (j >> 1);
                    dotR[ri] = fmaf(a, b, dotR[ri]);
                    n1R[ri]  = fmaf(a, a, n1R[ri]);
                    n2R[ri]  = fmaf(b, b, n2R[ri]);
                }
#pragma unroll
        for (int off = 1; off < 4; off <<= 1) {
#pragma unroll
            for (int ri = 0; ri < 4; ri++) {
                dotR[ri] += __shfl_xor_sync(0xffffffffu, dotR[ri], off);
                n1R[ri]  += __shfl_xor_sync(0xffffffffu, n1R[ri], off);
                n2R[ri]  += __shfl_xor_sync(0xffffffffu, n2R[ri], off);
            }
        }
        if (tg == 0) {
#pragma unroll
            for (int ri = 0; ri < 4; ri++) {
                const int r = wm * 32 + (ri >> 1) * 16 + g + (ri & 1) * 8;
                s_red[0][r][wn] = dotR[ri];
                s_red[1][r][wn] = n1R[ri];
                s_red[2][r][wn] = n2R[ri];
            }
        }
    }

    // ==================== Phase 3: GEMM3 on tensor cores (1-pass) ===========
    float acc3[2][2][4];
#pragma unroll
    for (int t = 0; t < 2; t++)
#pragma unroll
        for (int u = 0; u < 2; u++)
#pragma unroll
            for (int j = 0; j < 4; j++) acc3[t][u][j] = 0.0f;

    const uint32_t aOff3 = ((wm * 32 + ln16) * ST3 + lhalf * 8) * 2;
    const uint32_t bOff3_4 = (((wn * 16 + (lane & 7) + lhalf * 8) * ST3)
                              + (((lane >> 3) & 1) * 8)) * 2;
    char* A3 = Areg;                         // 64*136*2 = 17408 <= 36864
    uint32_t A3U = smem_u32(A3);
    uint32_t B3U = smem_u32(Breg);           // 64*136*2 = 17408 <= 36864

    __syncthreads();   // all warps done with phase-1 stages + s_red written

    for (int f = 0; f < 3; f++) {
        // prefetch W3 chunk f (64 x 128 halves)
#pragma unroll
        for (int it = 0; it < 4; it++) {
            int idx = tid + it * 256;
            int n_ = idx >> 4, cc = idx & 15;
            int off = (n_ * ST3 + cc * 8) * 2;
            cpasync16(B3U + off, g_w3 + n_ * 384 + f * 128 + cc * 8);
        }
        cpasync_commit();

        // write combined feature tile into A region (single fp16, stride ST3)
#pragma unroll
        for (int t = 0; t < 2; t++)
#pragma unroll
            for (int u = 0; u < 4; u++) {
                const int col = wn * 32 + u * 8 + tg * 2;
                const int r   = wm * 32 + t * 16 + g;
                float v[4];
#pragma unroll
                for (int j = 0; j < 4; j++) {
                    const float a = h1[t][u][j];
                    const float b = acc[t][u][j];
                    v[j] = (f == 0) ? a * b : (f == 1) ? fabsf(a - b) : a + b;
                }
                *reinterpret_cast<uint32_t*>(A3 + (r * ST3 + col) * 2)       = pack_h2(v[0], v[1]);
                *reinterpret_cast<uint32_t*>(A3 + ((r + 8) * ST3 + col) * 2) = pack_h2(v[2], v[3]);
            }
        cpasync_wait0();
        __syncthreads();

        // MMA over k=128 (8 steps), single pass; one B x4 covers both u's
#pragma unroll
        for (int ks = 0; ks < 8; ks++) {
            const uint32_t ko = ks * 32;
            uint32_t Ah[2][4], B01[4];
#pragma unroll
            for (int t = 0; t < 2; t++)
                ldmatrix_x4(Ah[t], A3U + aOff3 + (t * 16 * ST3) * 2 + ko);
            ldmatrix_x4(B01, B3U + bOff3_4 + ko);
#pragma unroll
            for (int t = 0; t < 2; t++) {
                mma_f16(acc3[t][0][0], acc3[t][0][1], acc3[t][0][2], acc3[t][0][3],
                        Ah[t][0], Ah[t][1], Ah[t][2], Ah[t][3], B01[0], B01[1]);
                mma_f16(acc3[t][1][0], acc3[t][1][1], acc3[t][1][2], acc3[t][1][3],
                        Ah[t][0], Ah[t][1], Ah[t][2], Ah[t][3], B01[2], B01[3]);
            }
        }
        __syncthreads();
    }

    // ==================== Phase 4: relu -> W4 -> head =======================
    {
        float slR[4];
#pragma unroll
        for (int ri = 0; ri < 4; ri++) slR[ri] = 0.0f;
#pragma unroll
        for (int u = 0; u < 2; u++) {
            const int col = wn * 16 + u * 8 + tg * 2;
            const float b30 = b3[col], b31 = b3[col + 1];
            const float w40 = W4[col], w41 = W4[col + 1];
#pragma unroll
            for (int t = 0; t < 2; t++) {
                slR[t * 2 + 0] += fmaxf(acc3[t][u][0] + b30, 0.0f) * w40
                                + fmaxf(acc3[t][u][1] + b31, 0.0f) * w41;
                slR[t * 2 + 1] += fmaxf(acc3[t][u][2] + b30, 0.0f) * w40
                                + fmaxf(acc3[t][u][3] + b31, 0.0f) * w41;
            }
        }
#pragma unroll
        for (int off = 1; off < 4; off <<= 1)
#pragma unroll
            for (int ri = 0; ri < 4; ri++)
                slR[ri] += __shfl_xor_sync(0xffffffffu, slR[ri], off);
        if (tg == 0) {
#pragma unroll
            for (int ri = 0; ri < 4; ri++) {
                const int r = wm * 32 + (ri >> 1) * 16 + g + (ri & 1) * 8;
                s_red[3][r][wn] = slR[ri];
            }
        }
    }
    __syncthreads();

    if (tid < 64) {
        float dot = 0.f, n1v = 0.f, n2v = 0.f, sl = 0.f;
#pragma unroll
        for (int w = 0; w < 4; w++) {
            dot += s_red[0][tid][w];
            n1v += s_red[1][tid][w];
            n2v += s_red[2][tid][w];
            sl  += s_red[3][tid][w];
        }
        const float inv1   = 1.0f / fmaxf(sqrtf(n1v), 1e-15f);
        const float inv2   = 1.0f / fmaxf(sqrtf(n2v), 1e-15f);
        const float s_math = fminf(fmaxf(dot * inv1 * inv2, 0.0f), 1.0f);
        const float sig    = 1.0f / (1.0f + expf(-(sl + b4[0])));
        const float fin    = alphap[0] * s_math + betap[0] * sig;
        out[row0 + tid] = fminf(fmaxf(fin, 0.0f), 1.0f);
    }
#undef F2_LDA
#undef F2_STA
#undef F2_CPB
}

// ---------------------------------------------------------------------------
extern "C" void kernel_launch(void* const* d_in, const int* in_sizes, int n_in,
                              void* d_out, int out_size)
{
    const float* x1      = (const float*)d_in[0];
    const float* x2      = (const float*)d_in[1];
    const float* W1      = (const float*)d_in[2];
    const float* b1      = (const float*)d_in[3];
    const float* gamma   = (const float*)d_in[4];
    const float* beta_bn = (const float*)d_in[5];
    const float* W2      = (const float*)d_in[6];
    const float* b2      = (const float*)d_in[7];
    const float* W3      = (const float*)d_in[8];
    const float* b3      = (const float*)d_in[9];
    const float* W4      = (const float*)d_in[10];
    const float* b4      = (const float*)d_in[11];
    const float* alphap  = (const float*)d_in[12];
    const float* betap   = (const float*)d_in[13];
    float* out = (float*)d_out;

    cudaFuncSetAttribute(gemm1_mma,
                         cudaFuncAttributeMaxDynamicSharedMemorySize, G1_DYN);
    cudaFuncSetAttribute(fused2,
                         cudaFuncAttributeMaxDynamicSharedMemorySize, F2_DYN);

    const int prep_elems = DK * HH + HH * H2 + 384 * O3;
    prep_weights<<<(prep_elems + 255) / 256, 256>>>(W1, W2, W3);

    dim3 g1(NRB1, 2);
    gemm1_mma<<<g1, 256, G1_DYN>>>(x1, x2, b1);

    stats_kernel<<<512, 256>>>(gamma, beta_bn);

    fused2<<<NRB2, 256, F2_DYN>>>(b2, b3, W4, b4, alphap, betap, out);
}